// round 3
// baseline (speedup 1.0000x reference)
#include <cuda_runtime.h>
#include <cstdint>

// ---------------------------------------------------------------------------
// Fully fused ShiftedWindowMSA (B=32, 56x56, EMB=256, 8 heads, 7x7 windows)
//   permute_w1:  w1 columns -> (head,which,e) contiguous, tf32-rounded
//   fused:       per CTA = (batch, window pair): stage x rows once, then per
//                head: GEMM qkv -> smem, attention, coalesced O scratch write
//   shuffle:     oscr[p][h*32+e] -> out[p][e*8+h]
// ---------------------------------------------------------------------------

#define WSZ 49

__device__ float g_w1p[256 * 768];
__device__ float g_b1p[768];
__device__ float g_oscr[(size_t)32 * 3136 * 256];   // 103 MB

// smem layout (floats)
#define OFF_A 0        // 112 x 260
#define OFF_B 29120    // 2 x 32 x 100
#define OFF_C 35520    // 2 x 64 x 100
#define OFF_S 48320    // 2 x 64 x 58
#define OFF_P 55744    // 176
#define SMEM_FLOATS 55920
#define ASTR 260
#define BSTR 100
#define CSTR 100
#define SSTR 58

__device__ __forceinline__ float to_tf32(float x) {
    uint32_t u;
    asm("cvt.rna.tf32.f32 %0, %1;" : "=r"(u) : "f"(x));
    return __uint_as_float(u);
}
__device__ __forceinline__ uint32_t fu(float x) { return __float_as_uint(x); }

__device__ __forceinline__ void mma_tf32(float c[4], uint32_t a0, uint32_t a1,
                                         uint32_t a2, uint32_t a3,
                                         uint32_t b0, uint32_t b1) {
    asm volatile(
        "mma.sync.aligned.m16n8k8.row.col.f32.tf32.tf32.f32 "
        "{%0,%1,%2,%3}, {%4,%5,%6,%7}, {%8,%9}, {%0,%1,%2,%3};"
        : "+f"(c[0]), "+f"(c[1]), "+f"(c[2]), "+f"(c[3])
        : "r"(a0), "r"(a1), "r"(a2), "r"(a3), "r"(b0), "r"(b1));
}

// ---------------------------------------------------------------------------
__global__ void permute_w1_kernel(const float* __restrict__ w1,
                                  const float* __restrict__ b1) {
    int idx = blockIdx.x * blockDim.x + threadIdx.x;
    if (idx < 256 * 768) {
        int k = idx / 768, jn = idx - k * 768;
        int g = jn >> 5, e = jn & 31;
        g_w1p[idx] = to_tf32(w1[k * 768 + e * 24 + g]);
    }
    if (idx < 768) {
        int g = idx >> 5, e = idx & 31;
        g_b1p[idx] = b1[e * 24 + g];
    }
}

// ---------------------------------------------------------------------------
__global__ __launch_bounds__(256, 1) void fused_kernel(
    const float* __restrict__ x, const float* __restrict__ pos) {
    extern __shared__ float sm[];

    const int tid = threadIdx.x;
    const int warpid = tid >> 5, lane = tid & 31;
    const int tg = lane >> 2, t4 = lane & 3;
    const int bid = blockIdx.x;
    const int base_b = bid >> 5;     // batch
    const int tpair = bid & 31;      // window pair index (wins 2t, 2t+1)

    // ---- stage A: 112 rows (2 windows of 49 + dup padding), tf32 ----
#pragma unroll 1
    for (int it = 0; it < 28; ++it) {
        int task = tid + it * 256;
        int mrow = task >> 6;
        int c4 = (task & 63) << 2;
        int win = (mrow >= 56);
        int wr = mrow - 56 * win;
        if (wr > 48) wr = 48;
        int wg = tpair * 2 + win;
        int wu = wg >> 3, wv = wg & 7;
        int wx = (wr * 9363) >> 16;
        int wy = wr - wx * 7;
        int y = wu * 7 + wx + 4; if (y >= 56) y -= 56;
        int xx = wv * 7 + wy + 4; if (xx >= 56) xx -= 56;
        float4 va = *reinterpret_cast<const float4*>(
            x + (size_t)((base_b * 56 + y) * 56 + xx) * 256 + c4);
        float4 t;
        t.x = to_tf32(va.x); t.y = to_tf32(va.y);
        t.z = to_tf32(va.z); t.w = to_tf32(va.w);
        *reinterpret_cast<float4*>(&sm[OFF_A + mrow * ASTR + c4]) = t;
    }
    for (int i = tid; i < 169; i += 256) sm[OFF_P + i] = pos[i];

    // precomputed B-chunk load slots (32 rows x 24 float4 = 768 tasks, 3/thread)
    int bkr[3], bc4[3];
#pragma unroll
    for (int i = 0; i < 3; ++i) {
        int f = tid + i * 256;
        bkr[i] = f / 24;
        bc4[i] = (f - bkr[i] * 24) * 4;
    }

    const float SCALE = 0.17677669529663687f;   // 1/sqrt(32)
    const float NEG_INF = __int_as_float(0xff800000u);

#pragma unroll 1
    for (int h = 0; h < 8; ++h) {
        const float* Bsrc = g_w1p + h * 96;

        // prefetch chunk 0 into buffer 0
#pragma unroll
        for (int i = 0; i < 3; ++i) {
            uint32_t sa = (uint32_t)__cvta_generic_to_shared(
                &sm[OFF_B + bkr[i] * BSTR + bc4[i]]);
            asm volatile("cp.async.cg.shared.global [%0], [%1], 16;\n"
                         :: "r"(sa), "l"(Bsrc + (size_t)bkr[i] * 768 + bc4[i]));
        }
        asm volatile("cp.async.commit_group;\n");

        float acc[12][4];
#pragma unroll
        for (int nt = 0; nt < 12; ++nt)
#pragma unroll
            for (int d = 0; d < 4; ++d) acc[nt][d] = 0.f;

        // ---- GEMM k-loop: 8 chunks of BK=32, double-buffered ----
#pragma unroll 1
        for (int kc = 0; kc < 8; ++kc) {
            __syncthreads();   // buffer (kc+1)&1 free for reuse
            if (kc < 7) {
#pragma unroll
                for (int i = 0; i < 3; ++i) {
                    uint32_t sa = (uint32_t)__cvta_generic_to_shared(
                        &sm[OFF_B + ((kc + 1) & 1) * 3200 + bkr[i] * BSTR + bc4[i]]);
                    asm volatile("cp.async.cg.shared.global [%0], [%1], 16;\n"
                                 :: "r"(sa),
                                    "l"(Bsrc + (size_t)((kc + 1) * 32 + bkr[i]) * 768 + bc4[i]));
                }
                asm volatile("cp.async.commit_group;\n");
                asm volatile("cp.async.wait_group 1;\n");
            } else {
                asm volatile("cp.async.wait_group 0;\n");
            }
            __syncthreads();

            if (warpid < 7) {
                const float* bb = sm + OFF_B + (kc & 1) * 3200;
                const float* aa = sm + OFF_A + (warpid * 16 + tg) * ASTR + kc * 32;
#pragma unroll
                for (int kk = 0; kk < 32; kk += 8) {
                    uint32_t a0 = fu(aa[kk + t4]);
                    uint32_t a1 = fu(aa[8 * ASTR + kk + t4]);
                    uint32_t a2 = fu(aa[kk + t4 + 4]);
                    uint32_t a3 = fu(aa[8 * ASTR + kk + t4 + 4]);
#pragma unroll
                    for (int nt = 0; nt < 12; ++nt) {
                        uint32_t b0 = fu(bb[(kk + t4) * BSTR + nt * 8 + tg]);
                        uint32_t b1 = fu(bb[(kk + t4 + 4) * BSTR + nt * 8 + tg]);
                        mma_tf32(acc[nt], a0, a1, a2, a3, b0, b1);
                    }
                }
            }
        }

        // ---- epilogue: write qkv tile to C smem (rows<49 real, 49..55 zero) ----
        if (warpid < 7) {
#pragma unroll
            for (int r2 = 0; r2 < 2; ++r2) {
                int mrow = warpid * 16 + tg + r2 * 8;
                int win = mrow >= 56;
                int wr = mrow - 56 * win;
                float* crow = sm + OFF_C + win * 6400 + wr * CSTR;
                bool valid = wr < 49;
#pragma unroll
                for (int nt = 0; nt < 12; ++nt) {
                    int col = nt * 8 + 2 * t4;
                    float v0 = 0.f, v1 = 0.f;
                    if (valid) {
                        v0 = to_tf32(acc[nt][r2 * 2 + 0] + g_b1p[h * 96 + col]);
                        v1 = to_tf32(acc[nt][r2 * 2 + 1] + g_b1p[h * 96 + col + 1]);
                    }
                    *reinterpret_cast<float2*>(&crow[col]) = make_float2(v0, v1);
                }
            }
        }
        __syncthreads();

        // ---- attention: warps 0-3 window 0, warps 4-7 window 1 ----
        const int winw = warpid >> 2;
        const int wl = warpid & 3;
        const int wg = tpair * 2 + winw;
        const int wu = wg >> 3, wv = wg & 7;
        const bool mu = (wu == 7), mv = (wv == 7);
        const float* Cw = sm + OFF_C + winw * 6400;
        float* Sw = sm + OFF_S + winw * 3712;
        const int r0 = wl * 16 + tg;

        // S = q k^T  (16 x 56 per warp)
        {
            float cS[7][4];
#pragma unroll
            for (int nt = 0; nt < 7; ++nt)
#pragma unroll
                for (int d = 0; d < 4; ++d) cS[nt][d] = 0.f;
#pragma unroll
            for (int kk = 0; kk < 32; kk += 8) {
                uint32_t a0 = fu(Cw[r0 * CSTR + kk + t4]);
                uint32_t a1 = fu(Cw[(r0 + 8) * CSTR + kk + t4]);
                uint32_t a2 = fu(Cw[r0 * CSTR + kk + t4 + 4]);
                uint32_t a3 = fu(Cw[(r0 + 8) * CSTR + kk + t4 + 4]);
#pragma unroll
                for (int nt = 0; nt < 7; ++nt) {
                    int n = nt * 8 + tg;
                    uint32_t b0 = fu(Cw[n * CSTR + 32 + kk + t4]);
                    uint32_t b1 = fu(Cw[n * CSTR + 32 + kk + t4 + 4]);
                    mma_tf32(cS[nt], a0, a1, a2, a3, b0, b1);
                }
            }
#pragma unroll
            for (int r2 = 0; r2 < 2; ++r2) {
                int row = r0 + r2 * 8;
                if (row < 49) {
                    int qt = (row * 9363) >> 16;
                    int ii = row - qt * 7;
                    bool pq = (qt >= 4), pi = (ii >= 4);
#pragma unroll
                    for (int nt = 0; nt < 7; ++nt) {
#pragma unroll
                        for (int d = 0; d < 2; ++d) {
                            int cc = nt * 8 + 2 * t4 + d;
                            if (cc < 49) {
                                int kt = (cc * 9363) >> 16;
                                int jj = cc - kt * 7;
                                float val = cS[nt][r2 * 2 + d] * SCALE
                                          + sm[OFF_P + (kt - qt + 6) * 13 + (jj - ii + 6)];
                                if (mu && (pq != (kt >= 4))) val = NEG_INF;
                                if (mv && (pi != (jj >= 4))) val = NEG_INF;
                                Sw[row * SSTR + cc] = val;
                            }
                        }
                    }
                }
            }
        }
        __syncthreads();

        // softmax (one thread per (window,row)), zero pad cols 49..55
        if (tid < 98) {
            int wn = tid >= 49;
            int r = tid - 49 * wn;
            float* rp = sm + OFF_S + wn * 3712 + r * SSTR;
            float m = rp[0];
#pragma unroll 7
            for (int k = 1; k < WSZ; ++k) m = fmaxf(m, rp[k]);
            float ssum = 0.f;
#pragma unroll 7
            for (int k = 0; k < WSZ; ++k) {
                float e = __expf(rp[k] - m);
                rp[k] = e;
                ssum += e;
            }
            float inv = 1.f / ssum;
#pragma unroll 7
            for (int k = 0; k < WSZ; ++k) rp[k] = to_tf32(rp[k] * inv);
#pragma unroll
            for (int k = WSZ; k < 56; ++k) rp[k] = 0.f;
        }
        __syncthreads();

        // O = P v  (16 x 32 per warp), write coalesced to oscr
        {
            float cO[4][4];
#pragma unroll
            for (int nt = 0; nt < 4; ++nt)
#pragma unroll
                for (int d = 0; d < 4; ++d) cO[nt][d] = 0.f;
#pragma unroll
            for (int kk = 0; kk < 56; kk += 8) {
                uint32_t a0 = fu(Sw[r0 * SSTR + kk + t4]);
                uint32_t a1 = fu(Sw[(r0 + 8) * SSTR + kk + t4]);
                uint32_t a2 = fu(Sw[r0 * SSTR + kk + t4 + 4]);
                uint32_t a3 = fu(Sw[(r0 + 8) * SSTR + kk + t4 + 4]);
#pragma unroll
                for (int nt = 0; nt < 4; ++nt) {
                    int n = nt * 8 + tg;
                    uint32_t b0 = fu(Cw[(kk + t4) * CSTR + 64 + n]);
                    uint32_t b1 = fu(Cw[(kk + t4 + 4) * CSTR + 64 + n]);
                    mma_tf32(cO[nt], a0, a1, a2, a3, b0, b1);
                }
            }
#pragma unroll
            for (int r2 = 0; r2 < 2; ++r2) {
                int row = r0 + r2 * 8;
                if (row < 49) {
                    int qt = (row * 9363) >> 16;
                    int ii = row - qt * 7;
                    int yo = wu * 7 + qt + 3; if (yo >= 56) yo -= 56;
                    int xo = wv * 7 + ii + 3; if (xo >= 56) xo -= 56;
                    float* op = g_oscr + (size_t)((base_b * 56 + yo) * 56 + xo) * 256 + h * 32;
#pragma unroll
                    for (int nt = 0; nt < 4; ++nt) {
                        int e0 = nt * 8 + 2 * t4;
                        *reinterpret_cast<float2*>(&op[e0]) =
                            make_float2(cO[nt][r2 * 2 + 0], cO[nt][r2 * 2 + 1]);
                    }
                }
            }
        }
        // next head's k-loop syncthreads orders C/S reuse
    }
}

// ---------------------------------------------------------------------------
// oscr[p][h*32+e] -> out[p][e*8+h], 32 pixels per block
// ---------------------------------------------------------------------------
__global__ __launch_bounds__(256) void shuffle_kernel(float* __restrict__ out) {
    const float* src = g_oscr + (size_t)blockIdx.x * (32 * 256);
    float* dst = out + (size_t)blockIdx.x * (32 * 256);
#pragma unroll
    for (int it = 0; it < 8; ++it) {
        int task = threadIdx.x + it * 256;
        int p = task >> 6;
        int c0 = (task & 63) << 2;
        const float* sp = src + p * 256;
        float4 v;
        v.x = sp[((c0 + 0) & 7) * 32 + ((c0 + 0) >> 3)];
        v.y = sp[((c0 + 1) & 7) * 32 + ((c0 + 1) >> 3)];
        v.z = sp[((c0 + 2) & 7) * 32 + ((c0 + 2) >> 3)];
        v.w = sp[((c0 + 3) & 7) * 32 + ((c0 + 3) >> 3)];
        *reinterpret_cast<float4*>(dst + p * 256 + c0) = v;
    }
}

// ---------------------------------------------------------------------------
extern "C" void kernel_launch(void* const* d_in, const int* in_sizes, int n_in,
                              void* d_out, int out_size) {
    const float* x   = (const float*)d_in[0];
    const float* w1  = (const float*)d_in[1];
    const float* b1  = (const float*)d_in[2];
    const float* pos = (const float*)d_in[3];
    float* out = (float*)d_out;

    static int configured = 0;
    if (!configured) {
        cudaFuncSetAttribute(fused_kernel,
                             cudaFuncAttributeMaxDynamicSharedMemorySize,
                             SMEM_FLOATS * 4);
        configured = 1;
    }

    permute_w1_kernel<<<768, 256>>>(w1, b1);
    fused_kernel<<<1024, 256, SMEM_FLOATS * 4>>>(x, pos);
    shuffle_kernel<<<3136, 256>>>(out);
}

// round 4
// speedup vs baseline: 1.4146x; 1.4146x over previous
#include <cuda_runtime.h>
#include <cstdint>

// ---------------------------------------------------------------------------
// ShiftedWindowMSA (B=32, 56x56, EMB=256, 8 heads, 7x7 windows)
//  cvt_x:      x -> tf32-rounded g_xt (enables cp.async GEMM, no cvt in loop)
//  permute_w1: w1 columns -> (head,which,e) contiguous, tf32-rounded
//  qkv_gemm:   cp.async double-buffered tf32 GEMM, epilogue scatters through
//              roll(-4)+window partition into g_scr (tf32-rounded, bias added)
//  attn:       tensor-core attention, in-register softmax (warp-local),
//              inverse roll(+3) output
// ---------------------------------------------------------------------------

#define WSZ 49
#define ROWSTRIDE 100352   // 64 windows * 49 * 32 per (b,g)

__device__ float g_scr[(size_t)32 * 24 * ROWSTRIDE];
__device__ float g_xt[(size_t)32 * 3136 * 256];
__device__ float g_w1p[256 * 768];
__device__ float g_b1p[768];

__device__ __forceinline__ float to_tf32(float x) {
    uint32_t u;
    asm("cvt.rna.tf32.f32 %0, %1;" : "=r"(u) : "f"(x));
    return __uint_as_float(u);
}
__device__ __forceinline__ uint32_t fu(float x) { return __float_as_uint(x); }

__device__ __forceinline__ void mma_tf32(float c[4], uint32_t a0, uint32_t a1,
                                         uint32_t a2, uint32_t a3,
                                         uint32_t b0, uint32_t b1) {
    asm volatile(
        "mma.sync.aligned.m16n8k8.row.col.f32.tf32.tf32.f32 "
        "{%0,%1,%2,%3}, {%4,%5,%6,%7}, {%8,%9}, {%0,%1,%2,%3};"
        : "+f"(c[0]), "+f"(c[1]), "+f"(c[2]), "+f"(c[3])
        : "r"(a0), "r"(a1), "r"(a2), "r"(a3), "r"(b0), "r"(b1));
}

// ---------------------------------------------------------------------------
__global__ __launch_bounds__(256) void cvt_x_kernel(const float* __restrict__ x) {
    // 6,422,528 float4 total: 3136 blocks * 256 threads * 8
    size_t base = (size_t)blockIdx.x * 2048 + threadIdx.x;
#pragma unroll
    for (int i = 0; i < 8; ++i) {
        size_t e = base + (size_t)i * 256;
        float4 v = reinterpret_cast<const float4*>(x)[e];
        float4 t;
        t.x = to_tf32(v.x); t.y = to_tf32(v.y);
        t.z = to_tf32(v.z); t.w = to_tf32(v.w);
        reinterpret_cast<float4*>(g_xt)[e] = t;
    }
}

__global__ void permute_w1_kernel(const float* __restrict__ w1,
                                  const float* __restrict__ b1) {
    int idx = blockIdx.x * blockDim.x + threadIdx.x;
    if (idx < 256 * 768) {
        int k = idx / 768, jn = idx - k * 768;
        int g = jn >> 5, e = jn & 31;
        g_w1p[idx] = to_tf32(w1[k * 768 + e * 24 + g]);
    }
    if (idx < 768) {
        int g = idx >> 5, e = idx & 31;
        g_b1p[idx] = b1[e * 24 + g];
    }
}

// ---------------------------------------------------------------------------
// Stage 2: QKV GEMM  C[100352,768] = g_xt @ g_w1p + b1p, cp.async 2-stage.
//   grid (6 n-tiles, 784 m-tiles): consecutive blocks reuse the A tile via L2.
// ---------------------------------------------------------------------------
#define ASTR 36
#define BSTR 136
#define A_FLOATS 4608    // 128*36
#define B_FLOATS 4352    // 32*136
#define GEMM_SMEM_BYTES ((2 * A_FLOATS + 2 * B_FLOATS) * 4)

__global__ __launch_bounds__(256) void qkv_gemm_kernel() {
    extern __shared__ float sm[];
    float* As[2] = { sm, sm + A_FLOATS };
    float* Bs[2] = { sm + 2 * A_FLOATS, sm + 2 * A_FLOATS + B_FLOATS };

    const int tid  = threadIdx.x;
    const int warp = tid >> 5, lane = tid & 31;
    const int tg = lane >> 2, t4 = lane & 3;
    const int wm0 = (warp >> 2) * 64;
    const int wn0 = (warp & 3) * 32;
    const int tile_m = blockIdx.y * 128;
    const int tile_n = blockIdx.x * 128;

    // per-thread load slots
    int arow[4], ac4[4], bkr[4], bc4[4];
#pragma unroll
    for (int j = 0; j < 4; ++j) {
        int f = tid + j * 256;
        arow[j] = f >> 3;  ac4[j] = (f & 7) * 4;
        bkr[j]  = f >> 5;  bc4[j] = (f & 31) * 4;
    }

    auto load_stage = [&](int ki, int s) {
#pragma unroll
        for (int j = 0; j < 4; ++j) {
            uint32_t sa = (uint32_t)__cvta_generic_to_shared(
                &As[s][arow[j] * ASTR + ac4[j]]);
            asm volatile("cp.async.cg.shared.global [%0], [%1], 16;\n"
                :: "r"(sa),
                   "l"(g_xt + (size_t)(tile_m + arow[j]) * 256 + ki + ac4[j]));
        }
#pragma unroll
        for (int j = 0; j < 4; ++j) {
            uint32_t sa = (uint32_t)__cvta_generic_to_shared(
                &Bs[s][bkr[j] * BSTR + bc4[j]]);
            asm volatile("cp.async.cg.shared.global [%0], [%1], 16;\n"
                :: "r"(sa),
                   "l"(g_w1p + (size_t)(ki + bkr[j]) * 768 + tile_n + bc4[j]));
        }
        asm volatile("cp.async.commit_group;\n");
    };

    float c[4][4][4];
#pragma unroll
    for (int a = 0; a < 4; ++a)
#pragma unroll
        for (int b = 0; b < 4; ++b)
#pragma unroll
            for (int d = 0; d < 4; ++d) c[a][b][d] = 0.f;

    load_stage(0, 0);

#pragma unroll 1
    for (int kc = 0; kc < 8; ++kc) {
        if (kc < 7) {
            load_stage((kc + 1) * 32, (kc + 1) & 1);
            asm volatile("cp.async.wait_group 1;\n");
        } else {
            asm volatile("cp.async.wait_group 0;\n");
        }
        __syncthreads();

        const float* aa = As[kc & 1];
        const float* bb = Bs[kc & 1];
#pragma unroll
        for (int kk = 0; kk < 32; kk += 8) {
            uint32_t a[4][4], bf[4][2];
#pragma unroll
            for (int mt = 0; mt < 4; ++mt) {
                int r = wm0 + mt * 16 + tg;
                a[mt][0] = fu(aa[r * ASTR + kk + t4]);
                a[mt][1] = fu(aa[(r + 8) * ASTR + kk + t4]);
                a[mt][2] = fu(aa[r * ASTR + kk + t4 + 4]);
                a[mt][3] = fu(aa[(r + 8) * ASTR + kk + t4 + 4]);
            }
#pragma unroll
            for (int nt = 0; nt < 4; ++nt) {
                int cn = wn0 + nt * 8 + tg;
                bf[nt][0] = fu(bb[(kk + t4) * BSTR + cn]);
                bf[nt][1] = fu(bb[(kk + t4 + 4) * BSTR + cn]);
            }
#pragma unroll
            for (int mt = 0; mt < 4; ++mt)
#pragma unroll
                for (int nt = 0; nt < 4; ++nt)
                    mma_tf32(c[mt][nt], a[mt][0], a[mt][1], a[mt][2], a[mt][3],
                             bf[nt][0], bf[nt][1]);
        }
        __syncthreads();   // protects buffer kc&1 before it is reloaded
    }

    // epilogue: scatter via roll(-4)+window partition; tf32-round(acc+bias)
    size_t rowbase[8];
#pragma unroll
    for (int mt = 0; mt < 4; ++mt) {
#pragma unroll
        for (int h = 0; h < 2; ++h) {
            int n = tile_m + wm0 + mt * 16 + tg + h * 8;
            int b = n / 3136;
            int r = n - b * 3136;
            int y = r / 56, xx = r - y * 56;
            int yr = (y + 52) % 56;
            int xr = (xx + 52) % 56;
            int u = yr / 7, wxr = yr - u * 7;
            int v = xr / 7, wyr = xr - v * 7;
            rowbase[mt * 2 + h] = (size_t)(b * 24) * ROWSTRIDE
                                + (size_t)(u * 8 + v) * (WSZ * 32)
                                + (size_t)(wxr * 7 + wyr) * 32;
        }
    }
#pragma unroll
    for (int nt = 0; nt < 4; ++nt) {
        int jn0 = tile_n + wn0 + nt * 8 + t4 * 2;
        float bias0 = g_b1p[jn0];
        float bias1 = g_b1p[jn0 + 1];
        int g0 = jn0 >> 5, e0 = jn0 & 31;
        size_t coff = (size_t)g0 * ROWSTRIDE + e0;
#pragma unroll
        for (int mt = 0; mt < 4; ++mt) {
            *reinterpret_cast<float2*>(&g_scr[rowbase[mt * 2 + 0] + coff]) =
                make_float2(to_tf32(c[mt][nt][0] + bias0),
                            to_tf32(c[mt][nt][1] + bias1));
            *reinterpret_cast<float2*>(&g_scr[rowbase[mt * 2 + 1] + coff]) =
                make_float2(to_tf32(c[mt][nt][2] + bias0),
                            to_tf32(c[mt][nt][3] + bias1));
        }
    }
}

// ---------------------------------------------------------------------------
// Stage 3: attention. 128 threads per (b, head, window). In-register softmax.
// ---------------------------------------------------------------------------
__global__ __launch_bounds__(128) void attn_kernel(const float* __restrict__ pos,
                                                   float* __restrict__ out) {
    __shared__ float sq[64 * 36];
    __shared__ float sk[56 * 36];
    __shared__ float sv[56 * 36];
    __shared__ float sS[64 * 58];
    __shared__ float sPos[169];

    const int tid = threadIdx.x;
    const int warp = tid >> 5, lane = tid & 31;
    const int tg = lane >> 2, t4 = lane & 3;
    const int bid = blockIdx.x;
    const int b    = bid >> 9;
    const int head = (bid >> 6) & 7;
    const int win  = bid & 63;
    const int u = win >> 3, v = win & 7;
    const bool mu = (u == 7), mv = (v == 7);

    const float* base = g_scr + (size_t)(b * 24 + head * 3) * ROWSTRIDE
                              + (size_t)win * (WSZ * 32);

    // load q,k,v (already tf32-rounded in g_scr)
    for (int t = tid; t < 1176; t += 128) {
        int which = t / 392;
        int rem = t - which * 392;
        int row = rem >> 3, c4 = (rem & 7) * 4;
        float4 val = *reinterpret_cast<const float4*>(
            base + (size_t)which * ROWSTRIDE + row * 32 + c4);
        float* dst = (which == 0) ? sq : (which == 1) ? sk : sv;
        *reinterpret_cast<float4*>(&dst[row * 36 + c4]) = val;
    }
    // zero pad rows (avoid NaN/Inf garbage feeding mma)
    for (int t = tid; t < 15 * 36; t += 128) sq[49 * 36 + t] = 0.f;
    for (int t = tid; t < 7 * 36; t += 128) { sk[49 * 36 + t] = 0.f; sv[49 * 36 + t] = 0.f; }
    for (int t = tid; t < 169; t += 128) sPos[t] = pos[t];
    __syncthreads();

    const int r0 = warp * 16 + tg;

    // ---- S = q k^T (16 x 56 per warp) ----
    float cS[7][4];
#pragma unroll
    for (int nt = 0; nt < 7; ++nt)
#pragma unroll
        for (int d = 0; d < 4; ++d) cS[nt][d] = 0.f;
#pragma unroll
    for (int kk = 0; kk < 32; kk += 8) {
        uint32_t a0 = fu(sq[r0 * 36 + kk + t4]);
        uint32_t a1 = fu(sq[(r0 + 8) * 36 + kk + t4]);
        uint32_t a2 = fu(sq[r0 * 36 + kk + t4 + 4]);
        uint32_t a3 = fu(sq[(r0 + 8) * 36 + kk + t4 + 4]);
#pragma unroll
        for (int nt = 0; nt < 7; ++nt) {
            int n = nt * 8 + tg;
            uint32_t b0 = fu(sk[n * 36 + kk + t4]);
            uint32_t b1 = fu(sk[n * 36 + kk + t4 + 4]);
            mma_tf32(cS[nt], a0, a1, a2, a3, b0, b1);
        }
    }

    // ---- in-register softmax (warp-local; shfl over the 4-lane quad) ----
    const float SCALE = 0.17677669529663687f;   // 1/sqrt(32)
    const float NEG_INF = __int_as_float(0xff800000u);
#pragma unroll
    for (int r2 = 0; r2 < 2; ++r2) {
        int row = r0 + r2 * 8;
        int qt = (row * 9363) >> 16;         // row / 7 (valid for row < 64)
        int ii = row - qt * 7;
        bool pq = (qt >= 4), pi = (ii >= 4);

        float vv[14];
        float mx = NEG_INF;
#pragma unroll
        for (int nt = 0; nt < 7; ++nt) {
#pragma unroll
            for (int d = 0; d < 2; ++d) {
                int cc = nt * 8 + 2 * t4 + d;
                float val = NEG_INF;
                if (cc < 49) {
                    int kt = (cc * 9363) >> 16;
                    int jj = cc - kt * 7;
                    val = cS[nt][r2 * 2 + d] * SCALE
                        + sPos[(kt - qt + 6) * 13 + (jj - ii + 6)];
                    if (mu && (pq != (kt >= 4))) val = NEG_INF;
                    if (mv && (pi != (jj >= 4))) val = NEG_INF;
                }
                vv[nt * 2 + d] = val;
                mx = fmaxf(mx, val);
            }
        }
        mx = fmaxf(mx, __shfl_xor_sync(0xffffffffu, mx, 1));
        mx = fmaxf(mx, __shfl_xor_sync(0xffffffffu, mx, 2));
        float sum = 0.f;
#pragma unroll
        for (int i = 0; i < 14; ++i) {
            float e = __expf(vv[i] - mx);
            vv[i] = e;
            sum += e;
        }
        sum += __shfl_xor_sync(0xffffffffu, sum, 1);
        sum += __shfl_xor_sync(0xffffffffu, sum, 2);
        float inv = 1.f / sum;
        if (row < 49) {
#pragma unroll
            for (int nt = 0; nt < 7; ++nt) {
#pragma unroll
                for (int d = 0; d < 2; ++d) {
                    int cc = nt * 8 + 2 * t4 + d;
                    sS[row * 58 + cc] = to_tf32(vv[nt * 2 + d] * inv);
                }
            }
        } else {
            // pad rows must be finite for the O-mma A operand
#pragma unroll
            for (int nt = 0; nt < 7; ++nt) {
#pragma unroll
                for (int d = 0; d < 2; ++d)
                    sS[row * 58 + nt * 8 + 2 * t4 + d] = 0.f;
            }
        }
    }
    __syncwarp();   // warp-local: each warp reads only its own 16 P rows

    // ---- O = P v (16 x 32 per warp) ----
    float cO[4][4];
#pragma unroll
    for (int nt = 0; nt < 4; ++nt)
#pragma unroll
        for (int d = 0; d < 4; ++d) cO[nt][d] = 0.f;
#pragma unroll
    for (int kk = 0; kk < 56; kk += 8) {
        uint32_t a0 = fu(sS[r0 * 58 + kk + t4]);
        uint32_t a1 = fu(sS[(r0 + 8) * 58 + kk + t4]);
        uint32_t a2 = fu(sS[r0 * 58 + kk + t4 + 4]);
        uint32_t a3 = fu(sS[(r0 + 8) * 58 + kk + t4 + 4]);
#pragma unroll
        for (int nt = 0; nt < 4; ++nt) {
            int n = nt * 8 + tg;
            uint32_t b0 = fu(sv[(kk + t4) * 36 + n]);
            uint32_t b1 = fu(sv[(kk + t4 + 4) * 36 + n]);
            mma_tf32(cO[nt], a0, a1, a2, a3, b0, b1);
        }
    }

    // ---- store with inverse roll(+3); channel = e*8 + head ----
#pragma unroll
    for (int r2 = 0; r2 < 2; ++r2) {
        int row = r0 + r2 * 8;
        if (row < 49) {
            int qt = (row * 9363) >> 16;
            int ii = row - qt * 7;
            int yo = u * 7 + qt + 3; if (yo >= 56) yo -= 56;
            int xo = v * 7 + ii + 3; if (xo >= 56) xo -= 56;
            float* op = out + ((size_t)((b * 56 + yo) * 56 + xo)) * 256 + head;
#pragma unroll
            for (int nt = 0; nt < 4; ++nt) {
                int e0 = nt * 8 + 2 * t4;
                op[(size_t)e0 * 8]       = cO[nt][r2 * 2 + 0];
                op[(size_t)(e0 + 1) * 8] = cO[nt][r2 * 2 + 1];
            }
        }
    }
}

// ---------------------------------------------------------------------------
extern "C" void kernel_launch(void* const* d_in, const int* in_sizes, int n_in,
                              void* d_out, int out_size) {
    const float* x   = (const float*)d_in[0];
    const float* w1  = (const float*)d_in[1];
    const float* b1  = (const float*)d_in[2];
    const float* pos = (const float*)d_in[3];
    float* out = (float*)d_out;

    static int configured = 0;
    if (!configured) {
        cudaFuncSetAttribute(qkv_gemm_kernel,
                             cudaFuncAttributeMaxDynamicSharedMemorySize,
                             GEMM_SMEM_BYTES);
        configured = 1;
    }

    cvt_x_kernel<<<3136, 256>>>(x);
    permute_w1_kernel<<<768, 256>>>(w1, b1);
    qkv_gemm_kernel<<<dim3(6, 784), 256, GEMM_SMEM_BYTES>>>();
    attn_kernel<<<16384, 128>>>(pos, out);
}

// round 5
// speedup vs baseline: 1.7478x; 1.2356x over previous
#include <cuda_runtime.h>
#include <cstdint>

// ---------------------------------------------------------------------------
// ShiftedWindowMSA (B=32, 56x56, EMB=256, 8 heads, 7x7 windows)
//  cvt_x:      x -> tf32-rounded g_xt
//  permute_w1: w1 columns -> (head,which,e) contiguous, tf32-rounded
//  qkv_gemm:   3-stage cp.async tf32 GEMM, epilogue scatters through
//              roll(-4)+window partition into g_scr (tf32-rounded, bias added)
//  attn:       tensor-core attention, in-register softmax + shfl-based
//              P fragment relayout (no P smem), inverse roll(+3) output
// ---------------------------------------------------------------------------

#define WSZ 49
#define ROWSTRIDE 100352   // 64 windows * 49 * 32 per (b,g)

__device__ float g_scr[(size_t)32 * 24 * ROWSTRIDE];
__device__ float g_xt[(size_t)32 * 3136 * 256];
__device__ float g_w1p[256 * 768];
__device__ float g_b1p[768];

__device__ __forceinline__ float to_tf32(float x) {
    uint32_t u;
    asm("cvt.rna.tf32.f32 %0, %1;" : "=r"(u) : "f"(x));
    return __uint_as_float(u);
}
__device__ __forceinline__ uint32_t fu(float x) { return __float_as_uint(x); }

__device__ __forceinline__ void mma_tf32(float c[4], uint32_t a0, uint32_t a1,
                                         uint32_t a2, uint32_t a3,
                                         uint32_t b0, uint32_t b1) {
    asm volatile(
        "mma.sync.aligned.m16n8k8.row.col.f32.tf32.tf32.f32 "
        "{%0,%1,%2,%3}, {%4,%5,%6,%7}, {%8,%9}, {%0,%1,%2,%3};"
        : "+f"(c[0]), "+f"(c[1]), "+f"(c[2]), "+f"(c[3])
        : "r"(a0), "r"(a1), "r"(a2), "r"(a3), "r"(b0), "r"(b1));
}

// ---------------------------------------------------------------------------
__global__ __launch_bounds__(256) void cvt_x_kernel(const float* __restrict__ x) {
    size_t base = (size_t)blockIdx.x * 2048 + threadIdx.x;
#pragma unroll
    for (int i = 0; i < 8; ++i) {
        size_t e = base + (size_t)i * 256;
        float4 v = reinterpret_cast<const float4*>(x)[e];
        float4 t;
        t.x = to_tf32(v.x); t.y = to_tf32(v.y);
        t.z = to_tf32(v.z); t.w = to_tf32(v.w);
        reinterpret_cast<float4*>(g_xt)[e] = t;
    }
}

__global__ void permute_w1_kernel(const float* __restrict__ w1,
                                  const float* __restrict__ b1) {
    int idx = blockIdx.x * blockDim.x + threadIdx.x;
    if (idx < 256 * 768) {
        int k = idx / 768, jn = idx - k * 768;
        int g = jn >> 5, e = jn & 31;
        g_w1p[idx] = to_tf32(w1[k * 768 + e * 24 + g]);
    }
    if (idx < 768) {
        int g = idx >> 5, e = idx & 31;
        g_b1p[idx] = b1[e * 24 + g];
    }
}

// ---------------------------------------------------------------------------
// Stage 2: QKV GEMM, 3-stage cp.async (prefetch depth 2).
// ---------------------------------------------------------------------------
#define ASTR 36
#define BSTR 136
#define A_FLOATS 4608    // 128*36
#define B_FLOATS 4352    // 32*136
#define STAGE_FLOATS (A_FLOATS + B_FLOATS)
#define GEMM_SMEM_BYTES (3 * STAGE_FLOATS * 4)

__global__ __launch_bounds__(256, 2) void qkv_gemm_kernel() {
    extern __shared__ float sm[];

    const int tid  = threadIdx.x;
    const int warp = tid >> 5, lane = tid & 31;
    const int tg = lane >> 2, t4 = lane & 3;
    const int wm0 = (warp >> 2) * 64;
    const int wn0 = (warp & 3) * 32;
    const int tile_m = blockIdx.y * 128;
    const int tile_n = blockIdx.x * 128;

    int arow[4], ac4[4], bkr[4], bc4[4];
#pragma unroll
    for (int j = 0; j < 4; ++j) {
        int f = tid + j * 256;
        arow[j] = f >> 3;  ac4[j] = (f & 7) * 4;
        bkr[j]  = f >> 5;  bc4[j] = (f & 31) * 4;
    }

    auto load_stage = [&](int ki, int s) {
        float* As = sm + s * STAGE_FLOATS;
        float* Bs = As + A_FLOATS;
#pragma unroll
        for (int j = 0; j < 4; ++j) {
            uint32_t sa = (uint32_t)__cvta_generic_to_shared(
                &As[arow[j] * ASTR + ac4[j]]);
            asm volatile("cp.async.cg.shared.global [%0], [%1], 16;\n"
                :: "r"(sa),
                   "l"(g_xt + (size_t)(tile_m + arow[j]) * 256 + ki + ac4[j]));
        }
#pragma unroll
        for (int j = 0; j < 4; ++j) {
            uint32_t sa = (uint32_t)__cvta_generic_to_shared(
                &Bs[bkr[j] * BSTR + bc4[j]]);
            asm volatile("cp.async.cg.shared.global [%0], [%1], 16;\n"
                :: "r"(sa),
                   "l"(g_w1p + (size_t)(ki + bkr[j]) * 768 + tile_n + bc4[j]));
        }
        asm volatile("cp.async.commit_group;\n");
    };

    float c[4][4][4];
#pragma unroll
    for (int a = 0; a < 4; ++a)
#pragma unroll
        for (int b = 0; b < 4; ++b)
#pragma unroll
            for (int d = 0; d < 4; ++d) c[a][b][d] = 0.f;

    load_stage(0, 0);
    load_stage(32, 1);

#pragma unroll 1
    for (int kc = 0; kc < 8; ++kc) {
        if (kc < 7) asm volatile("cp.async.wait_group 1;\n");
        else        asm volatile("cp.async.wait_group 0;\n");
        __syncthreads();
        if (kc + 2 < 8) load_stage((kc + 2) * 32, (kc + 2) % 3);

        const float* aa = sm + (kc % 3) * STAGE_FLOATS;
        const float* bb = aa + A_FLOATS;
#pragma unroll
        for (int kk = 0; kk < 32; kk += 8) {
            uint32_t a[4][4], bf[4][2];
#pragma unroll
            for (int mt = 0; mt < 4; ++mt) {
                int r = wm0 + mt * 16 + tg;
                a[mt][0] = fu(aa[r * ASTR + kk + t4]);
                a[mt][1] = fu(aa[(r + 8) * ASTR + kk + t4]);
                a[mt][2] = fu(aa[r * ASTR + kk + t4 + 4]);
                a[mt][3] = fu(aa[(r + 8) * ASTR + kk + t4 + 4]);
            }
#pragma unroll
            for (int nt = 0; nt < 4; ++nt) {
                int cn = wn0 + nt * 8 + tg;
                bf[nt][0] = fu(bb[(kk + t4) * BSTR + cn]);
                bf[nt][1] = fu(bb[(kk + t4 + 4) * BSTR + cn]);
            }
#pragma unroll
            for (int mt = 0; mt < 4; ++mt)
#pragma unroll
                for (int nt = 0; nt < 4; ++nt)
                    mma_tf32(c[mt][nt], a[mt][0], a[mt][1], a[mt][2], a[mt][3],
                             bf[nt][0], bf[nt][1]);
        }
    }

    // epilogue: scatter via roll(-4)+window partition; tf32-round(acc+bias)
    size_t rowbase[8];
#pragma unroll
    for (int mt = 0; mt < 4; ++mt) {
#pragma unroll
        for (int h = 0; h < 2; ++h) {
            int n = tile_m + wm0 + mt * 16 + tg + h * 8;
            int b = n / 3136;
            int r = n - b * 3136;
            int y = r / 56, xx = r - y * 56;
            int yr = (y + 52) % 56;
            int xr = (xx + 52) % 56;
            int u = yr / 7, wxr = yr - u * 7;
            int v = xr / 7, wyr = xr - v * 7;
            rowbase[mt * 2 + h] = (size_t)(b * 24) * ROWSTRIDE
                                + (size_t)(u * 8 + v) * (WSZ * 32)
                                + (size_t)(wxr * 7 + wyr) * 32;
        }
    }
#pragma unroll
    for (int nt = 0; nt < 4; ++nt) {
        int jn0 = tile_n + wn0 + nt * 8 + t4 * 2;
        float bias0 = g_b1p[jn0];
        float bias1 = g_b1p[jn0 + 1];
        int g0 = jn0 >> 5, e0 = jn0 & 31;
        size_t coff = (size_t)g0 * ROWSTRIDE + e0;
#pragma unroll
        for (int mt = 0; mt < 4; ++mt) {
            *reinterpret_cast<float2*>(&g_scr[rowbase[mt * 2 + 0] + coff]) =
                make_float2(to_tf32(c[mt][nt][0] + bias0),
                            to_tf32(c[mt][nt][1] + bias1));
            *reinterpret_cast<float2*>(&g_scr[rowbase[mt * 2 + 1] + coff]) =
                make_float2(to_tf32(c[mt][nt][2] + bias0),
                            to_tf32(c[mt][nt][3] + bias1));
        }
    }
}

// ---------------------------------------------------------------------------
// Stage 3: attention. 128 threads per (b, head, window).
//   In-register softmax on the S fragments; P->A fragment relayout via shfl.
// ---------------------------------------------------------------------------
__global__ __launch_bounds__(128, 6) void attn_kernel(const float* __restrict__ pos,
                                                      float* __restrict__ out) {
    __shared__ float sq[64 * 36];
    __shared__ float sk[56 * 36];
    __shared__ float sv[56 * 36];
    __shared__ float sPos[169];

    const int tid = threadIdx.x;
    const int warp = tid >> 5, lane = tid & 31;
    const int tg = lane >> 2, t4 = lane & 3;
    const int bid = blockIdx.x;
    const int b    = bid >> 9;
    const int head = (bid >> 6) & 7;
    const int win  = bid & 63;
    const int u = win >> 3, v = win & 7;
    const bool mu = (u == 7), mv = (v == 7);

    const float* base = g_scr + (size_t)(b * 24 + head * 3) * ROWSTRIDE
                              + (size_t)win * (WSZ * 32);

    for (int t = tid; t < 1176; t += 128) {
        int which = t / 392;
        int rem = t - which * 392;
        int row = rem >> 3, c4 = (rem & 7) * 4;
        float4 val = *reinterpret_cast<const float4*>(
            base + (size_t)which * ROWSTRIDE + row * 32 + c4);
        float* dst = (which == 0) ? sq : (which == 1) ? sk : sv;
        *reinterpret_cast<float4*>(&dst[row * 36 + c4]) = val;
    }
    for (int t = tid; t < 15 * 36; t += 128) sq[49 * 36 + t] = 0.f;
    for (int t = tid; t < 7 * 36; t += 128) { sk[49 * 36 + t] = 0.f; sv[49 * 36 + t] = 0.f; }
    for (int t = tid; t < 169; t += 128) sPos[t] = pos[t];
    __syncthreads();

    const int r0 = warp * 16 + tg;

    // ---- S = q k^T (16 x 56 per warp) ----
    float cS[7][4];
#pragma unroll
    for (int nt = 0; nt < 7; ++nt)
#pragma unroll
        for (int d = 0; d < 4; ++d) cS[nt][d] = 0.f;
#pragma unroll
    for (int kk = 0; kk < 32; kk += 8) {
        uint32_t a0 = fu(sq[r0 * 36 + kk + t4]);
        uint32_t a1 = fu(sq[(r0 + 8) * 36 + kk + t4]);
        uint32_t a2 = fu(sq[r0 * 36 + kk + t4 + 4]);
        uint32_t a3 = fu(sq[(r0 + 8) * 36 + kk + t4 + 4]);
#pragma unroll
        for (int nt = 0; nt < 7; ++nt) {
            int n = nt * 8 + tg;
            uint32_t b0 = fu(sk[n * 36 + kk + t4]);
            uint32_t b1 = fu(sk[n * 36 + kk + t4 + 4]);
            mma_tf32(cS[nt], a0, a1, a2, a3, b0, b1);
        }
    }

    // ---- in-register softmax (quad-local shfl reductions), in place ----
    const float SCALE = 0.17677669529663687f;   // 1/sqrt(32)
    const float NEG_INF = __int_as_float(0xff800000u);
#pragma unroll
    for (int r2 = 0; r2 < 2; ++r2) {
        int row = r0 + r2 * 8;
        int crow = row < 49 ? row : 48;      // clamp pad rows (discarded later)
        int qt = (crow * 9363) >> 16;
        int ii = crow - qt * 7;
        bool pq = (qt >= 4), pi = (ii >= 4);

        float mx = NEG_INF;
#pragma unroll
        for (int nt = 0; nt < 7; ++nt) {
#pragma unroll
            for (int d = 0; d < 2; ++d) {
                int cc = nt * 8 + 2 * t4 + d;
                float val = NEG_INF;
                if (cc < 49) {
                    int kt = (cc * 9363) >> 16;
                    int jj = cc - kt * 7;
                    val = cS[nt][r2 * 2 + d] * SCALE
                        + sPos[(kt - qt + 6) * 13 + (jj - ii + 6)];
                    if (mu && (pq != (kt >= 4))) val = NEG_INF;
                    if (mv && (pi != (jj >= 4))) val = NEG_INF;
                }
                cS[nt][r2 * 2 + d] = val;
                mx = fmaxf(mx, val);
            }
        }
        mx = fmaxf(mx, __shfl_xor_sync(0xffffffffu, mx, 1));
        mx = fmaxf(mx, __shfl_xor_sync(0xffffffffu, mx, 2));
        float sum = 0.f;
#pragma unroll
        for (int nt = 0; nt < 7; ++nt) {
#pragma unroll
            for (int d = 0; d < 2; ++d) {
                float e = __expf(cS[nt][r2 * 2 + d] - mx);
                cS[nt][r2 * 2 + d] = e;
                sum += e;
            }
        }
        sum += __shfl_xor_sync(0xffffffffu, sum, 1);
        sum += __shfl_xor_sync(0xffffffffu, sum, 2);
        float inv = 1.f / sum;
#pragma unroll
        for (int nt = 0; nt < 7; ++nt)
#pragma unroll
            for (int d = 0; d < 2; ++d)
                cS[nt][r2 * 2 + d] = to_tf32(cS[nt][r2 * 2 + d] * inv);
    }

    // ---- O = P v : relayout P C-frag -> A-frag via quad shfls ----
    float cO[4][4];
#pragma unroll
    for (int nt = 0; nt < 4; ++nt)
#pragma unroll
        for (int d = 0; d < 4; ++d) cO[nt][d] = 0.f;

    const int srcA = (lane & ~3) | (t4 >> 1);
    const int srcB = srcA | 2;
    const bool odd = (t4 & 1);
#pragma unroll
    for (int g = 0; g < 7; ++g) {
        int kk = g * 8;
        float s00 = __shfl_sync(0xffffffffu, cS[g][0], srcA);
        float s01 = __shfl_sync(0xffffffffu, cS[g][1], srcA);
        float s10 = __shfl_sync(0xffffffffu, cS[g][2], srcA);
        float s11 = __shfl_sync(0xffffffffu, cS[g][3], srcA);
        float t00 = __shfl_sync(0xffffffffu, cS[g][0], srcB);
        float t01 = __shfl_sync(0xffffffffu, cS[g][1], srcB);
        float t10 = __shfl_sync(0xffffffffu, cS[g][2], srcB);
        float t11 = __shfl_sync(0xffffffffu, cS[g][3], srcB);
        uint32_t a0 = fu(odd ? s01 : s00);   // P[row0][kk+t4]
        uint32_t a1 = fu(odd ? s11 : s10);   // P[row1][kk+t4]
        uint32_t a2 = fu(odd ? t01 : t00);   // P[row0][kk+t4+4]
        uint32_t a3 = fu(odd ? t11 : t10);   // P[row1][kk+t4+4]
#pragma unroll
        for (int nt = 0; nt < 4; ++nt) {
            int n = nt * 8 + tg;
            uint32_t b0 = fu(sv[(kk + t4) * 36 + n]);
            uint32_t b1 = fu(sv[(kk + t4 + 4) * 36 + n]);
            mma_tf32(cO[nt], a0, a1, a2, a3, b0, b1);
        }
    }

    // ---- store with inverse roll(+3); channel = e*8 + head ----
#pragma unroll
    for (int r2 = 0; r2 < 2; ++r2) {
        int row = r0 + r2 * 8;
        if (row < 49) {
            int qt = (row * 9363) >> 16;
            int ii = row - qt * 7;
            int yo = u * 7 + qt + 3; if (yo >= 56) yo -= 56;
            int xo = v * 7 + ii + 3; if (xo >= 56) xo -= 56;
            float* op = out + ((size_t)((b * 56 + yo) * 56 + xo)) * 256 + head;
#pragma unroll
            for (int nt = 0; nt < 4; ++nt) {
                int e0 = nt * 8 + 2 * t4;
                op[(size_t)e0 * 8]       = cO[nt][r2 * 2 + 0];
                op[(size_t)(e0 + 1) * 8] = cO[nt][r2 * 2 + 1];
            }
        }
    }
}

// ---------------------------------------------------------------------------
extern "C" void kernel_launch(void* const* d_in, const int* in_sizes, int n_in,
                              void* d_out, int out_size) {
    const float* x   = (const float*)d_in[0];
    const float* w1  = (const float*)d_in[1];
    const float* b1  = (const float*)d_in[2];
    const float* pos = (const float*)d_in[3];
    float* out = (float*)d_out;

    static int configured = 0;
    if (!configured) {
        cudaFuncSetAttribute(qkv_gemm_kernel,
                             cudaFuncAttributeMaxDynamicSharedMemorySize,
                             GEMM_SMEM_BYTES);
        configured = 1;
    }

    cvt_x_kernel<<<3136, 256>>>(x);
    permute_w1_kernel<<<768, 256>>>(w1, b1);
    qkv_gemm_kernel<<<dim3(6, 784), 256, GEMM_SMEM_BYTES>>>();
    attn_kernel<<<16384, 128>>>(pos, out);
}

// round 6
// speedup vs baseline: 1.9610x; 1.1220x over previous
#include <cuda_runtime.h>
#include <cstdint>

// ---------------------------------------------------------------------------
// ShiftedWindowMSA (B=32, 56x56, EMB=256, 8 heads, 7x7 windows)
//  permute_w1: w1 columns -> (head,which,e) contiguous, tf32-rounded
//  build_bias: bias+mask table, 4 window classes x 64 rows x 56 cols
//  qkv_gemm:   3-stage cp.async tf32 GEMM (raw x, in-register cvt), epilogue
//              scatters via roll(-4)+window partition into g_scr
//  attn:       tensor-core attention, table-driven softmax, shfl P relayout,
//              inverse roll(+3) output
// ---------------------------------------------------------------------------

#define WSZ 49
#define ROWSTRIDE 100352   // 64 windows * 49 * 32 per (b,g)

__device__ float g_scr[(size_t)32 * 24 * ROWSTRIDE];
__device__ float g_w1p[256 * 768];
__device__ float g_b1p[768];
__device__ float g_bias[4 * 64 * 56];

__device__ __forceinline__ float to_tf32(float x) {
    uint32_t u;
    asm("cvt.rna.tf32.f32 %0, %1;" : "=r"(u) : "f"(x));
    return __uint_as_float(u);
}
__device__ __forceinline__ uint32_t fu(float x) { return __float_as_uint(x); }

__device__ __forceinline__ void mma_tf32(float c[4], uint32_t a0, uint32_t a1,
                                         uint32_t a2, uint32_t a3,
                                         uint32_t b0, uint32_t b1) {
    asm volatile(
        "mma.sync.aligned.m16n8k8.row.col.f32.tf32.tf32.f32 "
        "{%0,%1,%2,%3}, {%4,%5,%6,%7}, {%8,%9}, {%0,%1,%2,%3};"
        : "+f"(c[0]), "+f"(c[1]), "+f"(c[2]), "+f"(c[3])
        : "r"(a0), "r"(a1), "r"(a2), "r"(a3), "r"(b0), "r"(b1));
}

// ---------------------------------------------------------------------------
__global__ void permute_w1_kernel(const float* __restrict__ w1,
                                  const float* __restrict__ b1) {
    int idx = blockIdx.x * blockDim.x + threadIdx.x;
    if (idx < 256 * 768) {
        int k = idx / 768, jn = idx - k * 768;
        int g = jn >> 5, e = jn & 31;
        g_w1p[idx] = to_tf32(w1[k * 768 + e * 24 + g]);
    }
    if (idx < 768) {
        int g = idx >> 5, e = idx & 31;
        g_b1p[idx] = b1[e * 24 + g];
    }
}

// bias+mask table: variant m = mu*2+mv; rows 49..63 duplicate row 48
__global__ void build_bias_kernel(const float* __restrict__ pos) {
    int idx = blockIdx.x * blockDim.x + threadIdx.x;
    if (idx >= 4 * 64 * 56) return;
    int m = idx / 3584;
    int rem = idx - m * 3584;
    int row = rem / 56, cc = rem - (rem / 56) * 56;
    bool mu = (m >> 1), mv = (m & 1);
    int crow = row < 49 ? row : 48;
    int qt = crow / 7, ii = crow - qt * 7;
    float val = __int_as_float(0xff800000u);
    if (cc < 49) {
        int kt = cc / 7, jj = cc - kt * 7;
        val = pos[(kt - qt + 6) * 13 + (jj - ii + 6)];
        if (mu && ((qt >= 4) != (kt >= 4))) val = __int_as_float(0xff800000u);
        if (mv && ((ii >= 4) != (jj >= 4))) val = __int_as_float(0xff800000u);
    }
    g_bias[idx] = val;
}

// ---------------------------------------------------------------------------
// Stage 2: QKV GEMM, 3-stage cp.async, raw-x load + in-register tf32 cvt.
// ---------------------------------------------------------------------------
#define ASTR 36
#define BSTR 136
#define A_FLOATS 4608    // 128*36
#define B_FLOATS 4352    // 32*136
#define STAGE_FLOATS (A_FLOATS + B_FLOATS)
#define GEMM_SMEM_BYTES (3 * STAGE_FLOATS * 4)

__global__ __launch_bounds__(256, 2) void qkv_gemm_kernel(const float* __restrict__ x) {
    extern __shared__ float sm[];

    const int tid  = threadIdx.x;
    const int warp = tid >> 5, lane = tid & 31;
    const int tg = lane >> 2, t4 = lane & 3;
    const int wm0 = (warp >> 2) * 64;
    const int wn0 = (warp & 3) * 32;
    const int tile_m = blockIdx.y * 128;
    const int tile_n = blockIdx.x * 128;

    int arow[4], ac4[4], bkr[4], bc4[4];
#pragma unroll
    for (int j = 0; j < 4; ++j) {
        int f = tid + j * 256;
        arow[j] = f >> 3;  ac4[j] = (f & 7) * 4;
        bkr[j]  = f >> 5;  bc4[j] = (f & 31) * 4;
    }

    auto load_stage = [&](int ki, int s) {
        float* As = sm + s * STAGE_FLOATS;
        float* Bs = As + A_FLOATS;
#pragma unroll
        for (int j = 0; j < 4; ++j) {
            uint32_t sa = (uint32_t)__cvta_generic_to_shared(
                &As[arow[j] * ASTR + ac4[j]]);
            asm volatile("cp.async.cg.shared.global [%0], [%1], 16;\n"
                :: "r"(sa),
                   "l"(x + (size_t)(tile_m + arow[j]) * 256 + ki + ac4[j]));
        }
#pragma unroll
        for (int j = 0; j < 4; ++j) {
            uint32_t sa = (uint32_t)__cvta_generic_to_shared(
                &Bs[bkr[j] * BSTR + bc4[j]]);
            asm volatile("cp.async.cg.shared.global [%0], [%1], 16;\n"
                :: "r"(sa),
                   "l"(g_w1p + (size_t)(ki + bkr[j]) * 768 + tile_n + bc4[j]));
        }
        asm volatile("cp.async.commit_group;\n");
    };

    float c[4][4][4];
#pragma unroll
    for (int a = 0; a < 4; ++a)
#pragma unroll
        for (int b = 0; b < 4; ++b)
#pragma unroll
            for (int d = 0; d < 4; ++d) c[a][b][d] = 0.f;

    load_stage(0, 0);
    load_stage(32, 1);

#pragma unroll 1
    for (int kc = 0; kc < 8; ++kc) {
        if (kc < 7) asm volatile("cp.async.wait_group 1;\n");
        else        asm volatile("cp.async.wait_group 0;\n");
        __syncthreads();
        if (kc + 2 < 8) load_stage((kc + 2) * 32, (kc + 2) % 3);

        const float* aa = sm + (kc % 3) * STAGE_FLOATS;
        const float* bb = aa + A_FLOATS;
#pragma unroll
        for (int kk = 0; kk < 32; kk += 8) {
            uint32_t a[4][4], bf[4][2];
#pragma unroll
            for (int mt = 0; mt < 4; ++mt) {
                int r = wm0 + mt * 16 + tg;
                a[mt][0] = fu(to_tf32(aa[r * ASTR + kk + t4]));
                a[mt][1] = fu(to_tf32(aa[(r + 8) * ASTR + kk + t4]));
                a[mt][2] = fu(to_tf32(aa[r * ASTR + kk + t4 + 4]));
                a[mt][3] = fu(to_tf32(aa[(r + 8) * ASTR + kk + t4 + 4]));
            }
#pragma unroll
            for (int nt = 0; nt < 4; ++nt) {
                int cn = wn0 + nt * 8 + tg;
                bf[nt][0] = fu(bb[(kk + t4) * BSTR + cn]);
                bf[nt][1] = fu(bb[(kk + t4 + 4) * BSTR + cn]);
            }
#pragma unroll
            for (int mt = 0; mt < 4; ++mt)
#pragma unroll
                for (int nt = 0; nt < 4; ++nt)
                    mma_tf32(c[mt][nt], a[mt][0], a[mt][1], a[mt][2], a[mt][3],
                             bf[nt][0], bf[nt][1]);
        }
    }

    // epilogue: scatter via roll(-4)+window partition; tf32-round(acc+bias)
    size_t rowbase[8];
#pragma unroll
    for (int mt = 0; mt < 4; ++mt) {
#pragma unroll
        for (int h = 0; h < 2; ++h) {
            int n = tile_m + wm0 + mt * 16 + tg + h * 8;
            int b = n / 3136;
            int r = n - b * 3136;
            int y = r / 56, xx = r - y * 56;
            int yr = (y + 52) % 56;
            int xr = (xx + 52) % 56;
            int u = yr / 7, wxr = yr - u * 7;
            int v = xr / 7, wyr = xr - v * 7;
            rowbase[mt * 2 + h] = (size_t)(b * 24) * ROWSTRIDE
                                + (size_t)(u * 8 + v) * (WSZ * 32)
                                + (size_t)(wxr * 7 + wyr) * 32;
        }
    }
#pragma unroll
    for (int nt = 0; nt < 4; ++nt) {
        int jn0 = tile_n + wn0 + nt * 8 + t4 * 2;
        float bias0 = g_b1p[jn0];
        float bias1 = g_b1p[jn0 + 1];
        int g0 = jn0 >> 5, e0 = jn0 & 31;
        size_t coff = (size_t)g0 * ROWSTRIDE + e0;
#pragma unroll
        for (int mt = 0; mt < 4; ++mt) {
            *reinterpret_cast<float2*>(&g_scr[rowbase[mt * 2 + 0] + coff]) =
                make_float2(to_tf32(c[mt][nt][0] + bias0),
                            to_tf32(c[mt][nt][1] + bias1));
            *reinterpret_cast<float2*>(&g_scr[rowbase[mt * 2 + 1] + coff]) =
                make_float2(to_tf32(c[mt][nt][2] + bias0),
                            to_tf32(c[mt][nt][3] + bias1));
        }
    }
}

// ---------------------------------------------------------------------------
// Stage 3: attention. 128 threads per (b, head, window).
//   Table-driven bias/mask, in-register softmax, shfl P relayout.
// ---------------------------------------------------------------------------
#define SVSTR 40   // (SVSTR*t4 + tg) % 32 == 8*t4+tg -> conflict-free

__global__ __launch_bounds__(128, 6) void attn_kernel(float* __restrict__ out) {
    __shared__ float sq[64 * 36];
    __shared__ float sk[56 * 36];
    __shared__ float sv[56 * SVSTR];

    const int tid = threadIdx.x;
    const int warp = tid >> 5, lane = tid & 31;
    const int tg = lane >> 2, t4 = lane & 3;
    const int bid = blockIdx.x;
    const int b    = bid >> 9;
    const int head = (bid >> 6) & 7;
    const int win  = bid & 63;
    const int u = win >> 3, v = win & 7;
    const int mclass = ((u == 7) ? 2 : 0) + ((v == 7) ? 1 : 0);
    const float* tbl = g_bias + mclass * 3584;

    const float* base = g_scr + (size_t)(b * 24 + head * 3) * ROWSTRIDE
                              + (size_t)win * (WSZ * 32);

    // load q,k,v: per array 392 float4 tasks (3 full rounds + 8-thread tail)
#pragma unroll
    for (int which = 0; which < 3; ++which) {
        const float* src = base + (size_t)which * ROWSTRIDE;
        float* dst = (which == 0) ? sq : (which == 1) ? sk : sv;
        int str = (which == 2) ? SVSTR : 36;
#pragma unroll
        for (int i = 0; i < 3; ++i) {
            int t = tid + i * 128;
            int row = t >> 3, c4 = (t & 7) * 4;
            float4 val = *reinterpret_cast<const float4*>(src + row * 32 + c4);
            *reinterpret_cast<float4*>(&dst[row * str + c4]) = val;
        }
        if (tid < 8) {   // row 48
            float4 val = *reinterpret_cast<const float4*>(src + 48 * 32 + tid * 4);
            *reinterpret_cast<float4*>(&dst[48 * str + tid * 4]) = val;
        }
    }
    // zero pad rows
    for (int t = tid; t < 15 * 36; t += 128) sq[49 * 36 + t] = 0.f;
    for (int t = tid; t < 7 * 36; t += 128) sk[49 * 36 + t] = 0.f;
    for (int t = tid; t < 7 * SVSTR; t += 128) sv[49 * SVSTR + t] = 0.f;
    __syncthreads();

    const int r0 = warp * 16 + tg;

    // ---- S = q k^T (16 x 56 per warp) ----
    float cS[7][4];
#pragma unroll
    for (int nt = 0; nt < 7; ++nt)
#pragma unroll
        for (int d = 0; d < 4; ++d) cS[nt][d] = 0.f;
#pragma unroll
    for (int kk = 0; kk < 32; kk += 8) {
        uint32_t a0 = fu(sq[r0 * 36 + kk + t4]);
        uint32_t a1 = fu(sq[(r0 + 8) * 36 + kk + t4]);
        uint32_t a2 = fu(sq[r0 * 36 + kk + t4 + 4]);
        uint32_t a3 = fu(sq[(r0 + 8) * 36 + kk + t4 + 4]);
#pragma unroll
        for (int nt = 0; nt < 7; ++nt) {
            int n = nt * 8 + tg;
            uint32_t b0 = fu(sk[n * 36 + kk + t4]);
            uint32_t b1 = fu(sk[n * 36 + kk + t4 + 4]);
            mma_tf32(cS[nt], a0, a1, a2, a3, b0, b1);
        }
    }

    // ---- table-driven scale+bias+mask, in-register softmax ----
    const float SCALE = 0.17677669529663687f;   // 1/sqrt(32)
    const float NEG_INF = __int_as_float(0xff800000u);
#pragma unroll
    for (int r2 = 0; r2 < 2; ++r2) {
        int row = r0 + r2 * 8;
        const float* trow = tbl + row * 56 + 2 * t4;

        float mx = NEG_INF;
#pragma unroll
        for (int nt = 0; nt < 7; ++nt) {
            float2 bv = *reinterpret_cast<const float2*>(trow + nt * 8);
            float v0 = fmaf(cS[nt][r2 * 2 + 0], SCALE, bv.x);
            float v1 = fmaf(cS[nt][r2 * 2 + 1], SCALE, bv.y);
            cS[nt][r2 * 2 + 0] = v0;
            cS[nt][r2 * 2 + 1] = v1;
            mx = fmaxf(mx, fmaxf(v0, v1));
        }
        mx = fmaxf(mx, __shfl_xor_sync(0xffffffffu, mx, 1));
        mx = fmaxf(mx, __shfl_xor_sync(0xffffffffu, mx, 2));
        float sum = 0.f;
#pragma unroll
        for (int nt = 0; nt < 7; ++nt) {
#pragma unroll
            for (int d = 0; d < 2; ++d) {
                float e = __expf(cS[nt][r2 * 2 + d] - mx);
                cS[nt][r2 * 2 + d] = e;
                sum += e;
            }
        }
        sum += __shfl_xor_sync(0xffffffffu, sum, 1);
        sum += __shfl_xor_sync(0xffffffffu, sum, 2);
        float inv = 1.f / sum;
#pragma unroll
        for (int nt = 0; nt < 7; ++nt)
#pragma unroll
            for (int d = 0; d < 2; ++d)
                cS[nt][r2 * 2 + d] = to_tf32(cS[nt][r2 * 2 + d] * inv);
    }

    // ---- O = P v : relayout P C-frag -> A-frag via quad shfls ----
    float cO[4][4];
#pragma unroll
    for (int nt = 0; nt < 4; ++nt)
#pragma unroll
        for (int d = 0; d < 4; ++d) cO[nt][d] = 0.f;

    const int srcA = (lane & ~3) | (t4 >> 1);
    const int srcB = srcA | 2;
    const bool odd = (t4 & 1);
#pragma unroll
    for (int g = 0; g < 7; ++g) {
        int kk = g * 8;
        float s00 = __shfl_sync(0xffffffffu, cS[g][0], srcA);
        float s01 = __shfl_sync(0xffffffffu, cS[g][1], srcA);
        float s10 = __shfl_sync(0xffffffffu, cS[g][2], srcA);
        float s11 = __shfl_sync(0xffffffffu, cS[g][3], srcA);
        float t00 = __shfl_sync(0xffffffffu, cS[g][0], srcB);
        float t01 = __shfl_sync(0xffffffffu, cS[g][1], srcB);
        float t10 = __shfl_sync(0xffffffffu, cS[g][2], srcB);
        float t11 = __shfl_sync(0xffffffffu, cS[g][3], srcB);
        uint32_t a0 = fu(odd ? s01 : s00);
        uint32_t a1 = fu(odd ? s11 : s10);
        uint32_t a2 = fu(odd ? t01 : t00);
        uint32_t a3 = fu(odd ? t11 : t10);
#pragma unroll
        for (int nt = 0; nt < 4; ++nt) {
            int n = nt * 8 + tg;
            uint32_t b0 = fu(sv[(kk + t4) * SVSTR + n]);
            uint32_t b1 = fu(sv[(kk + t4 + 4) * SVSTR + n]);
            mma_tf32(cO[nt], a0, a1, a2, a3, b0, b1);
        }
    }

    // ---- store with inverse roll(+3); channel = e*8 + head ----
#pragma unroll
    for (int r2 = 0; r2 < 2; ++r2) {
        int row = r0 + r2 * 8;
        if (row < 49) {
            int qt = (row * 9363) >> 16;
            int ii = row - qt * 7;
            int yo = u * 7 + qt + 3; if (yo >= 56) yo -= 56;
            int xo = v * 7 + ii + 3; if (xo >= 56) xo -= 56;
            float* op = out + ((size_t)((b * 56 + yo) * 56 + xo)) * 256 + head;
#pragma unroll
            for (int nt = 0; nt < 4; ++nt) {
                int e0 = nt * 8 + 2 * t4;
                op[(size_t)e0 * 8]       = cO[nt][r2 * 2 + 0];
                op[(size_t)(e0 + 1) * 8] = cO[nt][r2 * 2 + 1];
            }
        }
    }
}

// ---------------------------------------------------------------------------
extern "C" void kernel_launch(void* const* d_in, const int* in_sizes, int n_in,
                              void* d_out, int out_size) {
    const float* x   = (const float*)d_in[0];
    const float* w1  = (const float*)d_in[1];
    const float* b1  = (const float*)d_in[2];
    const float* pos = (const float*)d_in[3];
    float* out = (float*)d_out;

    static int configured = 0;
    if (!configured) {
        cudaFuncSetAttribute(qkv_gemm_kernel,
                             cudaFuncAttributeMaxDynamicSharedMemorySize,
                             GEMM_SMEM_BYTES);
        configured = 1;
    }

    permute_w1_kernel<<<768, 256>>>(w1, b1);
    build_bias_kernel<<<56, 256>>>(pos);
    qkv_gemm_kernel<<<dim3(6, 784), 256, GEMM_SMEM_BYTES>>>(x);
    attn_kernel<<<16384, 128>>>(out);
}

// round 7
// speedup vs baseline: 2.0763x; 1.0588x over previous
#include <cuda_runtime.h>
#include <cstdint>

// ---------------------------------------------------------------------------
// ShiftedWindowMSA (B=32, 56x56, EMB=256, 8 heads, 7x7 windows)
//  permute_w1: w1 columns -> (head,which,e) contiguous, tf32-rounded
//  build_bias: bias+mask table, 4 window classes x 64 rows x 56 cols
//  qkv_gemm:   3-stage cp.async tf32 GEMM, 64x64 warp tiles (4 warps/CTA),
//              epilogue scatters via roll(-4)+window partition into g_scr
//  attn:       tensor-core attention, table-driven softmax, shfl P relayout,
//              inverse roll(+3) output
// ---------------------------------------------------------------------------

#define WSZ 49
#define ROWSTRIDE 100352   // 64 windows * 49 * 32 per (b,g)

__device__ float g_scr[(size_t)32 * 24 * ROWSTRIDE];
__device__ float g_w1p[256 * 768];
__device__ float g_b1p[768];
__device__ float g_bias[4 * 64 * 56];

__device__ __forceinline__ float to_tf32(float x) {
    uint32_t u;
    asm("cvt.rna.tf32.f32 %0, %1;" : "=r"(u) : "f"(x));
    return __uint_as_float(u);
}
__device__ __forceinline__ uint32_t fu(float x) { return __float_as_uint(x); }

__device__ __forceinline__ void mma_tf32(float c[4], uint32_t a0, uint32_t a1,
                                         uint32_t a2, uint32_t a3,
                                         uint32_t b0, uint32_t b1) {
    asm volatile(
        "mma.sync.aligned.m16n8k8.row.col.f32.tf32.tf32.f32 "
        "{%0,%1,%2,%3}, {%4,%5,%6,%7}, {%8,%9}, {%0,%1,%2,%3};"
        : "+f"(c[0]), "+f"(c[1]), "+f"(c[2]), "+f"(c[3])
        : "r"(a0), "r"(a1), "r"(a2), "r"(a3), "r"(b0), "r"(b1));
}

// ---------------------------------------------------------------------------
__global__ void permute_w1_kernel(const float* __restrict__ w1,
                                  const float* __restrict__ b1) {
    int idx = blockIdx.x * blockDim.x + threadIdx.x;
    if (idx < 256 * 768) {
        int k = idx / 768, jn = idx - k * 768;
        int g = jn >> 5, e = jn & 31;
        g_w1p[idx] = to_tf32(w1[k * 768 + e * 24 + g]);
    }
    if (idx < 768) {
        int g = idx >> 5, e = idx & 31;
        g_b1p[idx] = b1[e * 24 + g];
    }
}

// bias+mask table: variant m = mu*2+mv; rows 49..63 duplicate row 48
__global__ void build_bias_kernel(const float* __restrict__ pos) {
    int idx = blockIdx.x * blockDim.x + threadIdx.x;
    if (idx >= 4 * 64 * 56) return;
    int m = idx / 3584;
    int rem = idx - m * 3584;
    int row = rem / 56, cc = rem - (rem / 56) * 56;
    bool mu = (m >> 1), mv = (m & 1);
    int crow = row < 49 ? row : 48;
    int qt = crow / 7, ii = crow - qt * 7;
    float val = __int_as_float(0xff800000u);
    if (cc < 49) {
        int kt = cc / 7, jj = cc - kt * 7;
        val = pos[(kt - qt + 6) * 13 + (jj - ii + 6)];
        if (mu && ((qt >= 4) != (kt >= 4))) val = __int_as_float(0xff800000u);
        if (mv && ((ii >= 4) != (jj >= 4))) val = __int_as_float(0xff800000u);
    }
    g_bias[idx] = val;
}

// ---------------------------------------------------------------------------
// Stage 2: QKV GEMM. Block 128x128, 4 warps, warp tile 64x64, BK=32,
//          3-stage cp.async, in-register tf32 cvt on A.
// ---------------------------------------------------------------------------
#define ASTR 36
#define BSTR 136
#define A_FLOATS 4608    // 128*36
#define B_FLOATS 4352    // 32*136
#define STAGE_FLOATS (A_FLOATS + B_FLOATS)
#define GEMM_SMEM_BYTES (3 * STAGE_FLOATS * 4)

__global__ __launch_bounds__(128, 2) void qkv_gemm_kernel(const float* __restrict__ x) {
    extern __shared__ float sm[];

    const int tid  = threadIdx.x;
    const int warp = tid >> 5, lane = tid & 31;
    const int tg = lane >> 2, t4 = lane & 3;
    const int wm0 = (warp >> 1) * 64;
    const int wn0 = (warp & 1) * 64;
    const int tile_m = blockIdx.y * 128;
    const int tile_n = blockIdx.x * 128;

    // load slots: A tile 128x32 = 1024 float4, B tile 32x128 = 1024 float4
    int arow[8], ac4[8], bkr[8], bc4[8];
#pragma unroll
    for (int j = 0; j < 8; ++j) {
        int f = tid + j * 128;
        arow[j] = f >> 3;  ac4[j] = (f & 7) * 4;
        bkr[j]  = f >> 5;  bc4[j] = (f & 31) * 4;
    }

    auto load_stage = [&](int ki, int s) {
        float* As = sm + s * STAGE_FLOATS;
        float* Bs = As + A_FLOATS;
#pragma unroll
        for (int j = 0; j < 8; ++j) {
            uint32_t sa = (uint32_t)__cvta_generic_to_shared(
                &As[arow[j] * ASTR + ac4[j]]);
            asm volatile("cp.async.cg.shared.global [%0], [%1], 16;\n"
                :: "r"(sa),
                   "l"(x + (size_t)(tile_m + arow[j]) * 256 + ki + ac4[j]));
        }
#pragma unroll
        for (int j = 0; j < 8; ++j) {
            uint32_t sa = (uint32_t)__cvta_generic_to_shared(
                &Bs[bkr[j] * BSTR + bc4[j]]);
            asm volatile("cp.async.cg.shared.global [%0], [%1], 16;\n"
                :: "r"(sa),
                   "l"(g_w1p + (size_t)(ki + bkr[j]) * 768 + tile_n + bc4[j]));
        }
        asm volatile("cp.async.commit_group;\n");
    };

    float c[4][8][4];
#pragma unroll
    for (int a = 0; a < 4; ++a)
#pragma unroll
        for (int b = 0; b < 8; ++b)
#pragma unroll
            for (int d = 0; d < 4; ++d) c[a][b][d] = 0.f;

    load_stage(0, 0);
    load_stage(32, 1);

#pragma unroll 1
    for (int kc = 0; kc < 8; ++kc) {
        if (kc < 7) asm volatile("cp.async.wait_group 1;\n");
        else        asm volatile("cp.async.wait_group 0;\n");
        __syncthreads();
        if (kc + 2 < 8) load_stage((kc + 2) * 32, (kc + 2) % 3);

        const float* aa = sm + (kc % 3) * STAGE_FLOATS;
        const float* bb = aa + A_FLOATS;
#pragma unroll
        for (int kk = 0; kk < 32; kk += 8) {
            uint32_t a[4][4];
#pragma unroll
            for (int mt = 0; mt < 4; ++mt) {
                int r = wm0 + mt * 16 + tg;
                a[mt][0] = fu(to_tf32(aa[r * ASTR + kk + t4]));
                a[mt][1] = fu(to_tf32(aa[(r + 8) * ASTR + kk + t4]));
                a[mt][2] = fu(to_tf32(aa[r * ASTR + kk + t4 + 4]));
                a[mt][3] = fu(to_tf32(aa[(r + 8) * ASTR + kk + t4 + 4]));
            }
#pragma unroll
            for (int nt = 0; nt < 8; ++nt) {
                int cn = wn0 + nt * 8 + tg;
                uint32_t b0 = fu(bb[(kk + t4) * BSTR + cn]);
                uint32_t b1 = fu(bb[(kk + t4 + 4) * BSTR + cn]);
#pragma unroll
                for (int mt = 0; mt < 4; ++mt)
                    mma_tf32(c[mt][nt], a[mt][0], a[mt][1], a[mt][2], a[mt][3],
                             b0, b1);
            }
        }
    }

    // epilogue: scatter via roll(-4)+window partition; tf32-round(acc+bias)
    size_t rowbase[8];
#pragma unroll
    for (int mt = 0; mt < 4; ++mt) {
#pragma unroll
        for (int h = 0; h < 2; ++h) {
            int n = tile_m + wm0 + mt * 16 + tg + h * 8;
            int b = n / 3136;
            int r = n - b * 3136;
            int y = r / 56, xx = r - y * 56;
            int yr = (y + 52) % 56;
            int xr = (xx + 52) % 56;
            int u = yr / 7, wxr = yr - u * 7;
            int v = xr / 7, wyr = xr - v * 7;
            rowbase[mt * 2 + h] = (size_t)(b * 24) * ROWSTRIDE
                                + (size_t)(u * 8 + v) * (WSZ * 32)
                                + (size_t)(wxr * 7 + wyr) * 32;
        }
    }
#pragma unroll
    for (int nt = 0; nt < 8; ++nt) {
        int jn0 = tile_n + wn0 + nt * 8 + t4 * 2;
        float bias0 = g_b1p[jn0];
        float bias1 = g_b1p[jn0 + 1];
        int g0 = jn0 >> 5, e0 = jn0 & 31;
        size_t coff = (size_t)g0 * ROWSTRIDE + e0;
#pragma unroll
        for (int mt = 0; mt < 4; ++mt) {
            *reinterpret_cast<float2*>(&g_scr[rowbase[mt * 2 + 0] + coff]) =
                make_float2(to_tf32(c[mt][nt][0] + bias0),
                            to_tf32(c[mt][nt][1] + bias1));
            *reinterpret_cast<float2*>(&g_scr[rowbase[mt * 2 + 1] + coff]) =
                make_float2(to_tf32(c[mt][nt][2] + bias0),
                            to_tf32(c[mt][nt][3] + bias1));
        }
    }
}

// ---------------------------------------------------------------------------
// Stage 3: attention. 128 threads per (b, head, window).
//   Table-driven bias/mask, in-register softmax, shfl P relayout.
// ---------------------------------------------------------------------------
#define SVSTR 40   // (SVSTR*t4 + tg) % 32 == 8*t4+tg -> conflict-free

__global__ __launch_bounds__(128, 6) void attn_kernel(float* __restrict__ out) {
    __shared__ float sq[64 * 36];
    __shared__ float sk[56 * 36];
    __shared__ float sv[56 * SVSTR];

    const int tid = threadIdx.x;
    const int warp = tid >> 5, lane = tid & 31;
    const int tg = lane >> 2, t4 = lane & 3;
    const int bid = blockIdx.x;
    const int b    = bid >> 9;
    const int head = (bid >> 6) & 7;
    const int win  = bid & 63;
    const int u = win >> 3, v = win & 7;
    const int mclass = ((u == 7) ? 2 : 0) + ((v == 7) ? 1 : 0);
    const float* tbl = g_bias + mclass * 3584;

    const float* base = g_scr + (size_t)(b * 24 + head * 3) * ROWSTRIDE
                              + (size_t)win * (WSZ * 32);

#pragma unroll
    for (int which = 0; which < 3; ++which) {
        const float* src = base + (size_t)which * ROWSTRIDE;
        float* dst = (which == 0) ? sq : (which == 1) ? sk : sv;
        int str = (which == 2) ? SVSTR : 36;
#pragma unroll
        for (int i = 0; i < 3; ++i) {
            int t = tid + i * 128;
            int row = t >> 3, c4 = (t & 7) * 4;
            float4 val = *reinterpret_cast<const float4*>(src + row * 32 + c4);
            *reinterpret_cast<float4*>(&dst[row * str + c4]) = val;
        }
        if (tid < 8) {   // row 48
            float4 val = *reinterpret_cast<const float4*>(src + 48 * 32 + tid * 4);
            *reinterpret_cast<float4*>(&dst[48 * str + tid * 4]) = val;
        }
    }
    for (int t = tid; t < 15 * 36; t += 128) sq[49 * 36 + t] = 0.f;
    for (int t = tid; t < 7 * 36; t += 128) sk[49 * 36 + t] = 0.f;
    for (int t = tid; t < 7 * SVSTR; t += 128) sv[49 * SVSTR + t] = 0.f;
    __syncthreads();

    const int r0 = warp * 16 + tg;

    // ---- S = q k^T (16 x 56 per warp) ----
    float cS[7][4];
#pragma unroll
    for (int nt = 0; nt < 7; ++nt)
#pragma unroll
        for (int d = 0; d < 4; ++d) cS[nt][d] = 0.f;
#pragma unroll
    for (int kk = 0; kk < 32; kk += 8) {
        uint32_t a0 = fu(sq[r0 * 36 + kk + t4]);
        uint32_t a1 = fu(sq[(r0 + 8) * 36 + kk + t4]);
        uint32_t a2 = fu(sq[r0 * 36 + kk + t4 + 4]);
        uint32_t a3 = fu(sq[(r0 + 8) * 36 + kk + t4 + 4]);
#pragma unroll
        for (int nt = 0; nt < 7; ++nt) {
            int n = nt * 8 + tg;
            uint32_t b0 = fu(sk[n * 36 + kk + t4]);
            uint32_t b1 = fu(sk[n * 36 + kk + t4 + 4]);
            mma_tf32(cS[nt], a0, a1, a2, a3, b0, b1);
        }
    }

    // ---- table-driven scale+bias+mask, in-register softmax ----
    const float SCALE = 0.17677669529663687f;   // 1/sqrt(32)
    const float NEG_INF = __int_as_float(0xff800000u);
#pragma unroll
    for (int r2 = 0; r2 < 2; ++r2) {
        int row = r0 + r2 * 8;
        const float* trow = tbl + row * 56 + 2 * t4;

        float mx = NEG_INF;
#pragma unroll
        for (int nt = 0; nt < 7; ++nt) {
            float2 bv = *reinterpret_cast<const float2*>(trow + nt * 8);
            float v0 = fmaf(cS[nt][r2 * 2 + 0], SCALE, bv.x);
            float v1 = fmaf(cS[nt][r2 * 2 + 1], SCALE, bv.y);
            cS[nt][r2 * 2 + 0] = v0;
            cS[nt][r2 * 2 + 1] = v1;
            mx = fmaxf(mx, fmaxf(v0, v1));
        }
        mx = fmaxf(mx, __shfl_xor_sync(0xffffffffu, mx, 1));
        mx = fmaxf(mx, __shfl_xor_sync(0xffffffffu, mx, 2));
        float sum = 0.f;
#pragma unroll
        for (int nt = 0; nt < 7; ++nt) {
#pragma unroll
            for (int d = 0; d < 2; ++d) {
                float e = __expf(cS[nt][r2 * 2 + d] - mx);
                cS[nt][r2 * 2 + d] = e;
                sum += e;
            }
        }
        sum += __shfl_xor_sync(0xffffffffu, sum, 1);
        sum += __shfl_xor_sync(0xffffffffu, sum, 2);
        float inv = 1.f / sum;
#pragma unroll
        for (int nt = 0; nt < 7; ++nt)
#pragma unroll
            for (int d = 0; d < 2; ++d)
                cS[nt][r2 * 2 + d] = to_tf32(cS[nt][r2 * 2 + d] * inv);
    }

    // ---- O = P v : relayout P C-frag -> A-frag via quad shfls ----
    float cO[4][4];
#pragma unroll
    for (int nt = 0; nt < 4; ++nt)
#pragma unroll
        for (int d = 0; d < 4; ++d) cO[nt][d] = 0.f;

    const int srcA = (lane & ~3) | (t4 >> 1);
    const int srcB = srcA | 2;
    const bool odd = (t4 & 1);
#pragma unroll
    for (int g = 0; g < 7; ++g) {
        int kk = g * 8;
        float s00 = __shfl_sync(0xffffffffu, cS[g][0], srcA);
        float s01 = __shfl_sync(0xffffffffu, cS[g][1], srcA);
        float s10 = __shfl_sync(0xffffffffu, cS[g][2], srcA);
        float s11 = __shfl_sync(0xffffffffu, cS[g][3], srcA);
        float t00 = __shfl_sync(0xffffffffu, cS[g][0], srcB);
        float t01 = __shfl_sync(0xffffffffu, cS[g][1], srcB);
        float t10 = __shfl_sync(0xffffffffu, cS[g][2], srcB);
        float t11 = __shfl_sync(0xffffffffu, cS[g][3], srcB);
        uint32_t a0 = fu(odd ? s01 : s00);
        uint32_t a1 = fu(odd ? s11 : s10);
        uint32_t a2 = fu(odd ? t01 : t00);
        uint32_t a3 = fu(odd ? t11 : t10);
#pragma unroll
        for (int nt = 0; nt < 4; ++nt) {
            int n = nt * 8 + tg;
            uint32_t b0 = fu(sv[(kk + t4) * SVSTR + n]);
            uint32_t b1 = fu(sv[(kk + t4 + 4) * SVSTR + n]);
            mma_tf32(cO[nt], a0, a1, a2, a3, b0, b1);
        }
    }

    // ---- store with inverse roll(+3); channel = e*8 + head ----
#pragma unroll
    for (int r2 = 0; r2 < 2; ++r2) {
        int row = r0 + r2 * 8;
        if (row < 49) {
            int qt = (row * 9363) >> 16;
            int ii = row - qt * 7;
            int yo = u * 7 + qt + 3; if (yo >= 56) yo -= 56;
            int xo = v * 7 + ii + 3; if (xo >= 56) xo -= 56;
            float* op = out + ((size_t)((b * 56 + yo) * 56 + xo)) * 256 + head;
#pragma unroll
            for (int nt = 0; nt < 4; ++nt) {
                int e0 = nt * 8 + 2 * t4;
                op[(size_t)e0 * 8]       = cO[nt][r2 * 2 + 0];
                op[(size_t)(e0 + 1) * 8] = cO[nt][r2 * 2 + 1];
            }
        }
    }
}

// ---------------------------------------------------------------------------
extern "C" void kernel_launch(void* const* d_in, const int* in_sizes, int n_in,
                              void* d_out, int out_size) {
    const float* x   = (const float*)d_in[0];
    const float* w1  = (const float*)d_in[1];
    const float* b1  = (const float*)d_in[2];
    const float* pos = (const float*)d_in[3];
    float* out = (float*)d_out;

    static int configured = 0;
    if (!configured) {
        cudaFuncSetAttribute(qkv_gemm_kernel,
                             cudaFuncAttributeMaxDynamicSharedMemorySize,
                             GEMM_SMEM_BYTES);
        configured = 1;
    }

    permute_w1_kernel<<<768, 256>>>(w1, b1);
    build_bias_kernel<<<56, 256>>>(pos);
    qkv_gemm_kernel<<<dim3(6, 784), 128, GEMM_SMEM_BYTES>>>(x);
    attn_kernel<<<16384, 128>>>(out);
}

// round 9
// speedup vs baseline: 2.4423x; 1.1763x over previous
#include <cuda_runtime.h>
#include <cuda_fp16.h>
#include <cstdint>

// ---------------------------------------------------------------------------
// ShiftedWindowMSA (B=32, 56x56, EMB=256, 8 heads, 7x7 windows)
//  cvt_x:      x -> fp16 g_xh (10-bit mantissa, same as tf32)
//  permute_w1: w1 -> g_w1phT [768][256] fp16, K-major, (head,which,e) order
//  build_bias: bias+mask table, 4 window classes x 64 rows x 56 cols
//  qkv_gemm:   fp16 mma.m16n8k16 GEMM (2x tf32 rate), 3-stage cp.async,
//              64x64 warp tiles; epilogue scatters via roll(-4)+window
//  attn:       tf32 mma attention (unchanged from round 6/7)
// ---------------------------------------------------------------------------

#define WSZ 49
#define ROWSTRIDE 100352   // 64 windows * 49 * 32 per (b,g)

__device__ float  g_scr[(size_t)32 * 24 * ROWSTRIDE];
__device__ __half g_xh[(size_t)32 * 3136 * 256];
__device__ __half g_w1phT[768 * 256];
__device__ float  g_b1p[768];
__device__ float  g_bias[4 * 64 * 56];

__device__ __forceinline__ float to_tf32(float x) {
    uint32_t u;
    asm("cvt.rna.tf32.f32 %0, %1;" : "=r"(u) : "f"(x));
    return __uint_as_float(u);
}
__device__ __forceinline__ uint32_t fu(float x) { return __float_as_uint(x); }

__device__ __forceinline__ void mma_tf32(float c[4], uint32_t a0, uint32_t a1,
                                         uint32_t a2, uint32_t a3,
                                         uint32_t b0, uint32_t b1) {
    asm volatile(
        "mma.sync.aligned.m16n8k8.row.col.f32.tf32.tf32.f32 "
        "{%0,%1,%2,%3}, {%4,%5,%6,%7}, {%8,%9}, {%0,%1,%2,%3};"
        : "+f"(c[0]), "+f"(c[1]), "+f"(c[2]), "+f"(c[3])
        : "r"(a0), "r"(a1), "r"(a2), "r"(a3), "r"(b0), "r"(b1));
}

__device__ __forceinline__ void mma_f16(float c[4], uint32_t a0, uint32_t a1,
                                        uint32_t a2, uint32_t a3,
                                        uint32_t b0, uint32_t b1) {
    asm volatile(
        "mma.sync.aligned.m16n8k16.row.col.f32.f16.f16.f32 "
        "{%0,%1,%2,%3}, {%4,%5,%6,%7}, {%8,%9}, {%0,%1,%2,%3};"
        : "+f"(c[0]), "+f"(c[1]), "+f"(c[2]), "+f"(c[3])
        : "r"(a0), "r"(a1), "r"(a2), "r"(a3), "r"(b0), "r"(b1));
}

// ---------------------------------------------------------------------------
// x -> fp16. 3136 blocks * 256 threads * 4 groups of 8 floats.
// ---------------------------------------------------------------------------
__global__ __launch_bounds__(256) void cvt_x_kernel(const float* __restrict__ x) {
    size_t base = (size_t)blockIdx.x * 1024 + threadIdx.x;
#pragma unroll
    for (int i = 0; i < 4; ++i) {
        size_t g = base + (size_t)i * 256;
        float4 v0 = reinterpret_cast<const float4*>(x)[g * 2];
        float4 v1 = reinterpret_cast<const float4*>(x)[g * 2 + 1];
        __half2 h0 = __floats2half2_rn(v0.x, v0.y);
        __half2 h1 = __floats2half2_rn(v0.z, v0.w);
        __half2 h2 = __floats2half2_rn(v1.x, v1.y);
        __half2 h3 = __floats2half2_rn(v1.z, v1.w);
        uint4 o;
        o.x = *reinterpret_cast<uint32_t*>(&h0);
        o.y = *reinterpret_cast<uint32_t*>(&h1);
        o.z = *reinterpret_cast<uint32_t*>(&h2);
        o.w = *reinterpret_cast<uint32_t*>(&h3);
        reinterpret_cast<uint4*>(g_xh)[g] = o;
    }
}

// g_w1phT[jn][k] = fp16(w1[k][e*24+g]),  jn = g*32+e  ([N,K] K-major)
__global__ void permute_w1_kernel(const float* __restrict__ w1,
                                  const float* __restrict__ b1) {
    int idx = blockIdx.x * blockDim.x + threadIdx.x;
    if (idx < 768 * 256) {
        int jn = idx >> 8, k = idx & 255;
        int g = jn >> 5, e = jn & 31;
        g_w1phT[idx] = __float2half_rn(w1[k * 768 + e * 24 + g]);
    }
    if (idx < 768) {
        int g = idx >> 5, e = idx & 31;
        g_b1p[idx] = b1[e * 24 + g];
    }
}

__global__ void build_bias_kernel(const float* __restrict__ pos) {
    int idx = blockIdx.x * blockDim.x + threadIdx.x;
    if (idx >= 4 * 64 * 56) return;
    int m = idx / 3584;
    int rem = idx - m * 3584;
    int row = rem / 56, cc = rem - (rem / 56) * 56;
    bool mu = (m >> 1), mv = (m & 1);
    int crow = row < 49 ? row : 48;
    int qt = crow / 7, ii = crow - qt * 7;
    float val = __int_as_float(0xff800000u);
    if (cc < 49) {
        int kt = cc / 7, jj = cc - kt * 7;
        val = pos[(kt - qt + 6) * 13 + (jj - ii + 6)];
        if (mu && ((qt >= 4) != (kt >= 4))) val = __int_as_float(0xff800000u);
        if (mv && ((ii >= 4) != (jj >= 4))) val = __int_as_float(0xff800000u);
    }
    g_bias[idx] = val;
}

// ---------------------------------------------------------------------------
// Stage 2: fp16 QKV GEMM. Block 128x128, 4 warps, warp tile 64x64, BK=32,
//   3-stage cp.async. A,B both K-major [128 rows][32 halves], stride 40 halves.
// ---------------------------------------------------------------------------
#define HSTR 40                       // halves per row (80 B)
#define STAGE_HALVES (2 * 128 * HSTR) // A + B per stage
#define GEMM_SMEM_BYTES (3 * STAGE_HALVES * 2)

__global__ __launch_bounds__(128, 2) void qkv_gemm_kernel() {
    extern __shared__ __half smh[];

    const int tid  = threadIdx.x;
    const int warp = tid >> 5, lane = tid & 31;
    const int tg = lane >> 2, t4 = lane & 3;
    const int wm0 = (warp >> 1) * 64;
    const int wn0 = (warp & 1) * 64;
    const int tile_m = blockIdx.y * 128;
    const int tile_n = blockIdx.x * 128;

    // load slots: A 128 rows x 4 x 16B units, then B same (1024 tasks, 8/thread)
    const int lrow = tid >> 2;          // shared by all j: row advances by 32
    const int lunit = (tid & 3) * 8;    // halves offset within row

    auto load_stage = [&](int kc, int s) {
        __half* As = smh + s * STAGE_HALVES;
        __half* Bs = As + 128 * HSTR;
        const __half* asrc = g_xh + (size_t)(tile_m + lrow) * 256 + kc * 32 + lunit;
        const __half* bsrc = g_w1phT + (size_t)(tile_n + lrow) * 256 + kc * 32 + lunit;
#pragma unroll
        for (int j = 0; j < 4; ++j) {
            uint32_t sa = (uint32_t)__cvta_generic_to_shared(
                &As[(lrow + j * 32) * HSTR + lunit]);
            asm volatile("cp.async.cg.shared.global [%0], [%1], 16;"
                         :: "r"(sa), "l"(asrc + (size_t)j * 32 * 256));
        }
#pragma unroll
        for (int j = 0; j < 4; ++j) {
            uint32_t sa = (uint32_t)__cvta_generic_to_shared(
                &Bs[(lrow + j * 32) * HSTR + lunit]);
            asm volatile("cp.async.cg.shared.global [%0], [%1], 16;"
                         :: "r"(sa), "l"(bsrc + (size_t)j * 32 * 256));
        }
        asm volatile("cp.async.commit_group;");
    };

    float c[4][8][4];
#pragma unroll
    for (int a = 0; a < 4; ++a)
#pragma unroll
        for (int b = 0; b < 8; ++b)
#pragma unroll
            for (int d = 0; d < 4; ++d) c[a][b][d] = 0.f;

    load_stage(0, 0);
    load_stage(1, 1);

#pragma unroll 1
    for (int kc = 0; kc < 8; ++kc) {
        if (kc < 7) asm volatile("cp.async.wait_group 1;");
        else        asm volatile("cp.async.wait_group 0;");
        __syncthreads();
        if (kc + 2 < 8) load_stage(kc + 2, (kc + 2) % 3);

        const __half* aa = smh + (kc % 3) * STAGE_HALVES;
        const __half* bb = aa + 128 * HSTR;
#pragma unroll
        for (int kk = 0; kk < 32; kk += 16) {
            uint32_t a[4][4];
#pragma unroll
            for (int mt = 0; mt < 4; ++mt) {
                int r = wm0 + mt * 16 + tg;
                a[mt][0] = *reinterpret_cast<const uint32_t*>(&aa[r * HSTR + kk + 2 * t4]);
                a[mt][1] = *reinterpret_cast<const uint32_t*>(&aa[(r + 8) * HSTR + kk + 2 * t4]);
                a[mt][2] = *reinterpret_cast<const uint32_t*>(&aa[r * HSTR + kk + 2 * t4 + 8]);
                a[mt][3] = *reinterpret_cast<const uint32_t*>(&aa[(r + 8) * HSTR + kk + 2 * t4 + 8]);
            }
#pragma unroll
            for (int nt = 0; nt < 8; ++nt) {
                int n = wn0 + nt * 8 + tg;
                uint32_t b0 = *reinterpret_cast<const uint32_t*>(&bb[n * HSTR + kk + 2 * t4]);
                uint32_t b1 = *reinterpret_cast<const uint32_t*>(&bb[n * HSTR + kk + 2 * t4 + 8]);
#pragma unroll
                for (int mt = 0; mt < 4; ++mt)
                    mma_f16(c[mt][nt], a[mt][0], a[mt][1], a[mt][2], a[mt][3],
                            b0, b1);
            }
        }
    }

    // epilogue: scatter via roll(-4)+window partition; tf32-round(acc+bias)
    size_t rowbase[8];
#pragma unroll
    for (int mt = 0; mt < 4; ++mt) {
#pragma unroll
        for (int h = 0; h < 2; ++h) {
            int n = tile_m + wm0 + mt * 16 + tg + h * 8;
            int b = n / 3136;
            int r = n - b * 3136;
            int y = r / 56, xx = r - y * 56;
            int yr = (y + 52) % 56;
            int xr = (xx + 52) % 56;
            int u = yr / 7, wxr = yr - u * 7;
            int v = xr / 7, wyr = xr - v * 7;
            rowbase[mt * 2 + h] = (size_t)(b * 24) * ROWSTRIDE
                                + (size_t)(u * 8 + v) * (WSZ * 32)
                                + (size_t)(wxr * 7 + wyr) * 32;
        }
    }
#pragma unroll
    for (int nt = 0; nt < 8; ++nt) {
        int jn0 = tile_n + wn0 + nt * 8 + t4 * 2;
        float bias0 = g_b1p[jn0];
        float bias1 = g_b1p[jn0 + 1];
        int g0 = jn0 >> 5, e0 = jn0 & 31;
        size_t coff = (size_t)g0 * ROWSTRIDE + e0;
#pragma unroll
        for (int mt = 0; mt < 4; ++mt) {
            *reinterpret_cast<float2*>(&g_scr[rowbase[mt * 2 + 0] + coff]) =
                make_float2(to_tf32(c[mt][nt][0] + bias0),
                            to_tf32(c[mt][nt][1] + bias1));
            *reinterpret_cast<float2*>(&g_scr[rowbase[mt * 2 + 1] + coff]) =
                make_float2(to_tf32(c[mt][nt][2] + bias0),
                            to_tf32(c[mt][nt][3] + bias1));
        }
    }
}

// ---------------------------------------------------------------------------
// Stage 3: attention (unchanged). 128 threads per (b, head, window).
// ---------------------------------------------------------------------------
#define SVSTR 40

__global__ __launch_bounds__(128, 6) void attn_kernel(float* __restrict__ out) {
    __shared__ float sq[64 * 36];
    __shared__ float sk[56 * 36];
    __shared__ float sv[56 * SVSTR];

    const int tid = threadIdx.x;
    const int warp = tid >> 5, lane = tid & 31;
    const int tg = lane >> 2, t4 = lane & 3;
    const int bid = blockIdx.x;
    const int b    = bid >> 9;
    const int head = (bid >> 6) & 7;
    const int win  = bid & 63;
    const int u = win >> 3, v = win & 7;
    const int mclass = ((u == 7) ? 2 : 0) + ((v == 7) ? 1 : 0);
    const float* tbl = g_bias + mclass * 3584;

    const float* base = g_scr + (size_t)(b * 24 + head * 3) * ROWSTRIDE
                              + (size_t)win * (WSZ * 32);

#pragma unroll
    for (int which = 0; which < 3; ++which) {
        const float* src = base + (size_t)which * ROWSTRIDE;
        float* dst = (which == 0) ? sq : (which == 1) ? sk : sv;
        int str = (which == 2) ? SVSTR : 36;
#pragma unroll
        for (int i = 0; i < 3; ++i) {
            int t = tid + i * 128;
            int row = t >> 3, c4 = (t & 7) * 4;
            float4 val = *reinterpret_cast<const float4*>(src + row * 32 + c4);
            *reinterpret_cast<float4*>(&dst[row * str + c4]) = val;
        }
        if (tid < 8) {
            float4 val = *reinterpret_cast<const float4*>(src + 48 * 32 + tid * 4);
            *reinterpret_cast<float4*>(&dst[48 * str + tid * 4]) = val;
        }
    }
    for (int t = tid; t < 15 * 36; t += 128) sq[49 * 36 + t] = 0.f;
    for (int t = tid; t < 7 * 36; t += 128) sk[49 * 36 + t] = 0.f;
    for (int t = tid; t < 7 * SVSTR; t += 128) sv[49 * SVSTR + t] = 0.f;
    __syncthreads();

    const int r0 = warp * 16 + tg;

    float cS[7][4];
#pragma unroll
    for (int nt = 0; nt < 7; ++nt)
#pragma unroll
        for (int d = 0; d < 4; ++d) cS[nt][d] = 0.f;
#pragma unroll
    for (int kk = 0; kk < 32; kk += 8) {
        uint32_t a0 = fu(sq[r0 * 36 + kk + t4]);
        uint32_t a1 = fu(sq[(r0 + 8) * 36 + kk + t4]);
        uint32_t a2 = fu(sq[r0 * 36 + kk + t4 + 4]);
        uint32_t a3 = fu(sq[(r0 + 8) * 36 + kk + t4 + 4]);
#pragma unroll
        for (int nt = 0; nt < 7; ++nt) {
            int n = nt * 8 + tg;
            uint32_t b0 = fu(sk[n * 36 + kk + t4]);
            uint32_t b1 = fu(sk[n * 36 + kk + t4 + 4]);
            mma_tf32(cS[nt], a0, a1, a2, a3, b0, b1);
        }
    }

    const float SCALE = 0.17677669529663687f;
    const float NEG_INF = __int_as_float(0xff800000u);
#pragma unroll
    for (int r2 = 0; r2 < 2; ++r2) {
        int row = r0 + r2 * 8;
        const float* trow = tbl + row * 56 + 2 * t4;

        float mx = NEG_INF;
#pragma unroll
        for (int nt = 0; nt < 7; ++nt) {
            float2 bv = *reinterpret_cast<const float2*>(trow + nt * 8);
            float v0 = fmaf(cS[nt][r2 * 2 + 0], SCALE, bv.x);
            float v1 = fmaf(cS[nt][r2 * 2 + 1], SCALE, bv.y);
            cS[nt][r2 * 2 + 0] = v0;
            cS[nt][r2 * 2 + 1] = v1;
            mx = fmaxf(mx, fmaxf(v0, v1));
        }
        mx = fmaxf(mx, __shfl_xor_sync(0xffffffffu, mx, 1));
        mx = fmaxf(mx, __shfl_xor_sync(0xffffffffu, mx, 2));
        float sum = 0.f;
#pragma unroll
        for (int nt = 0; nt < 7; ++nt) {
#pragma unroll
            for (int d = 0; d < 2; ++d) {
                float e = __expf(cS[nt][r2 * 2 + d] - mx);
                cS[nt][r2 * 2 + d] = e;
                sum += e;
            }
        }
        sum += __shfl_xor_sync(0xffffffffu, sum, 1);
        sum += __shfl_xor_sync(0xffffffffu, sum, 2);
        float inv = 1.f / sum;
#pragma unroll
        for (int nt = 0; nt < 7; ++nt)
#pragma unroll
            for (int d = 0; d < 2; ++d)
                cS[nt][r2 * 2 + d] = to_tf32(cS[nt][r2 * 2 + d] * inv);
    }

    float cO[4][4];
#pragma unroll
    for (int nt = 0; nt < 4; ++nt)
#pragma unroll
        for (int d = 0; d < 4; ++d) cO[nt][d] = 0.f;

    const int srcA = (lane & ~3) | (t4 >> 1);
    const int srcB = srcA | 2;
    const bool odd = (t4 & 1);
#pragma unroll
    for (int g = 0; g < 7; ++g) {
        int kk = g * 8;
        float s00 = __shfl_sync(0xffffffffu, cS[g][0], srcA);
        float s01 = __shfl_sync(0xffffffffu, cS[g][1], srcA);
        float s10 = __shfl_sync(0xffffffffu, cS[g][2], srcA);
        float s11 = __shfl_sync(0xffffffffu, cS[g][3], srcA);
        float t00 = __shfl_sync(0xffffffffu, cS[g][0], srcB);
        float t01 = __shfl_sync(0xffffffffu, cS[g][1], srcB);
        float t10 = __shfl_sync(0xffffffffu, cS[g][2], srcB);
        float t11 = __shfl_sync(0xffffffffu, cS[g][3], srcB);
        uint32_t a0 = fu(odd ? s01 : s00);
        uint32_t a1 = fu(odd ? s11 : s10);
        uint32_t a2 = fu(odd ? t01 : t00);
        uint32_t a3 = fu(odd ? t11 : t10);
#pragma unroll
        for (int nt = 0; nt < 4; ++nt) {
            int n = nt * 8 + tg;
            uint32_t b0 = fu(sv[(kk + t4) * SVSTR + n]);
            uint32_t b1 = fu(sv[(kk + t4 + 4) * SVSTR + n]);
            mma_tf32(cO[nt], a0, a1, a2, a3, b0, b1);
        }
    }

#pragma unroll
    for (int r2 = 0; r2 < 2; ++r2) {
        int row = r0 + r2 * 8;
        if (row < 49) {
            int qt = (row * 9363) >> 16;
            int ii = row - qt * 7;
            int yo = u * 7 + qt + 3; if (yo >= 56) yo -= 56;
            int xo = v * 7 + ii + 3; if (xo >= 56) xo -= 56;
            float* op = out + ((size_t)((b * 56 + yo) * 56 + xo)) * 256 + head;
#pragma unroll
            for (int nt = 0; nt < 4; ++nt) {
                int e0 = nt * 8 + 2 * t4;
                op[(size_t)e0 * 8]       = cO[nt][r2 * 2 + 0];
                op[(size_t)(e0 + 1) * 8] = cO[nt][r2 * 2 + 1];
            }
        }
    }
}

// ---------------------------------------------------------------------------
extern "C" void kernel_launch(void* const* d_in, const int* in_sizes, int n_in,
                              void* d_out, int out_size) {
    const float* x   = (const float*)d_in[0];
    const float* w1  = (const float*)d_in[1];
    const float* b1  = (const float*)d_in[2];
    const float* pos = (const float*)d_in[3];
    float* out = (float*)d_out;

    static int configured = 0;
    if (!configured) {
        cudaFuncSetAttribute(qkv_gemm_kernel,
                             cudaFuncAttributeMaxDynamicSharedMemorySize,
                             GEMM_SMEM_BYTES);
        configured = 1;
    }

    cvt_x_kernel<<<3136, 256>>>(x);
    permute_w1_kernel<<<768, 256>>>(w1, b1);
    build_bias_kernel<<<56, 256>>>(pos);
    qkv_gemm_kernel<<<dim3(6, 784), 128, GEMM_SMEM_BYTES>>>();
    attn_kernel<<<16384, 128>>>(out);
}